// round 5
// baseline (speedup 1.0000x reference)
#include <cuda_runtime.h>

#define HH 256
#define WW 256
#define NBLK 63
#define CAND 81
#define KSEL 16
#define NIMG 8
#define RP 68   // padded smem row stride (floats)

__device__ __align__(16) float g_T[NIMG * NBLK * NBLK * 64];
__device__ __align__(16) float g_nc[NIMG * HH * WW * 2];

// ---------------------------------------------------------------------------
__global__ void zero_kernel() {
    int idx = blockIdx.x * blockDim.x + threadIdx.x;
    ((float4*)g_nc)[idx] = make_float4(0.f, 0.f, 0.f, 0.f);
}

// ---------------------------------------------------------------------------
// 8x8 DCT of every patch
// ---------------------------------------------------------------------------
__global__ void dct_kernel(const float* __restrict__ x) {
    __shared__ float sD[64];
    __shared__ float sp[4][64];
    __shared__ float st[4][64];
    int t = threadIdx.x;
    if (t < 64) {
        int k = t >> 3, i = t & 7;
        float v = cospif((float)((2 * i + 1) * k) / 16.0f) * 0.5f;
        if (k == 0) v = 0.35355339059327373f;
        sD[t] = v;
    }
    int grp = t >> 6;
    int lt = t & 63;
    int pid = blockIdx.x * 4 + grp;
    bool valid = pid < NIMG * NBLK * NBLK;
    int img = 0, bi = 0, bj = 0;
    if (valid) {
        img = pid / (NBLK * NBLK);
        int r = pid % (NBLK * NBLK);
        bi = r / NBLK; bj = r % NBLK;
    }
    __syncthreads();
    if (valid) {
        int b = lt >> 3, c = lt & 7;
        float v = x[img * (HH * WW) + (bi * 4 + b) * WW + (bj * 4 + c)];
        sp[grp][lt] = fminf(fmaxf(v, 0.0f), 1.0f);
    }
    __syncthreads();
    if (valid) {
        int a = lt >> 3, c = lt & 7;
        float acc = 0.f;
#pragma unroll
        for (int b = 0; b < 8; b++) acc += sD[a * 8 + b] * sp[grp][b * 8 + c];
        st[grp][lt] = acc;
    }
    __syncthreads();
    if (valid) {
        int a = lt >> 3, d = lt & 7;
        float acc = 0.f;
#pragma unroll
        for (int c = 0; c < 8; c++) acc += st[grp][a * 8 + c] * sD[d * 8 + c];
        g_T[pid * 64 + lt] = acc;
    }
}

// ---------------------------------------------------------------------------
// Main pipeline: 256 threads, 4 reference blocks in parallel.
// GB aliases the front of nbT (nbT dead after its stage-4 reads).
// smem = 32736 B < 48KB static cap.
// ---------------------------------------------------------------------------
__global__ void __launch_bounds__(256) bm3d_kernel() {
    __shared__ float nbT[9 * 12 * RP];          // 29376 B; front 4352 floats reused as GB
    __shared__ float sDK[256];
    __shared__ float sD[64];
    __shared__ float sdist[4 * CAND];
    __shared__ int selOff[4][KSEL];
    __shared__ int selYs[4][KSEL];
    __shared__ int selXs[4][KSEL];
    __shared__ int snnz[4];
    float* GB = nbT;                             // alias (64*RP = 4352 floats needed)

    int t = threadIdx.x;
    int i = blockIdx.y;
    int j0 = blockIdx.x * 4;
    int img = blockIdx.z;
    int nb = min(4, NBLK - j0);

    {   // DCT-16 matrix: one entry per thread
        int k = t >> 4, ii = t & 15;
        float v = cospif((float)((2 * ii + 1) * k) / 32.0f) * 0.35355339059327373f;
        if (k == 0) v = 0.25f;
        sDK[t] = v;
    }
    if (t < 64) {
        int k = t >> 3, ii = t & 7;
        float v = cospif((float)((2 * ii + 1) * k) / 16.0f) * 0.5f;
        if (k == 0) v = 0.35355339059327373f;
        sD[t] = v;
    }
    if (t >= 64 && t < 68) snnz[t - 64] = 0;

    const float* Timg = g_T + img * (NBLK * NBLK * 64);
    for (int idx = t; idx < 9 * 12 * 64; idx += 256) {
        int r = idx / (12 * 64);
        int s = (idx >> 6) % 12;
        int p = idx & 63;
        int ci = min(max(i - 4 + r, 0), NBLK - 1);
        int cj = min(max(j0 - 4 + s, 0), NBLK - 1);
        nbT[(r * 12 + s) * RP + p] = Timg[(ci * NBLK + cj) * 64 + p];
    }
    __syncthreads();   // [1]

    int lane = t & 31, warp = t >> 5;
    float* ncImg = g_nc + img * (HH * WW * 2);
    int C = nb * CAND;

    // ---- distances: 8-lane groups, 4 candidates per warp per iteration ----
    {
        int grpL = lane >> 3;
        int sub  = lane & 7;
        for (int cb = warp * 4; cb < C; cb += 32) {
            int cid = min(cb + grpL, C - 1);
            int jb = cid / CAND;
            int c  = cid % CAND;
            int rr = c / 9;
            int sc = jb + (c % 9);
            const float* cp = &nbT[(rr * 12 + sc) * RP + sub * 8];
            const float* rp = &nbT[(4 * 12 + jb + 4) * RP + sub * 8];
            float acc = 0.f;
#pragma unroll
            for (int q = 0; q < 4; q++) {
                float2 cv = *(const float2*)(cp + q * 2);
                float2 rv = *(const float2*)(rp + q * 2);
                float d0 = cv.x - rv.x, d1 = cv.y - rv.y;
                acc += d0 * d0 + d1 * d1;
            }
            acc += __shfl_xor_sync(0xffffffffu, acc, 1);
            acc += __shfl_xor_sync(0xffffffffu, acc, 2);
            acc += __shfl_xor_sync(0xffffffffu, acc, 4);
            if (sub == 0 && cb + grpL < C) sdist[cid] = acc;
        }
    }
    __syncthreads();   // [2]

    // ---- rank-based top-16 per block (ties -> lower candidate index) ----
    for (int u = t; u < C; u += 256) {
        int jb = u / CAND;
        int c  = u % CAND;
        const float* ds = &sdist[jb * CAND];
        float my = ds[c];
        int rank = 0;
        for (int cc = 0; cc < CAND; cc++) {
            float dc = ds[cc];
            rank += (dc < my) || (dc == my && cc < c);
        }
        if (rank < KSEL) {
            int rr = c / 9;
            int dxi = c % 9;
            selOff[jb][rank] = (rr * 12 + jb + dxi) * RP;
            int ci = min(max(i - 4 + rr, 0), NBLK - 1);
            int cj = min(max(j0 + jb - 4 + dxi, 0), NBLK - 1);
            selYs[jb][rank] = ci * 4;
            selXs[jb][rank] = cj * 4;
        }
    }
    __syncthreads();   // [3]

    // ---- group-axis chain fully in registers:
    //      gather -> DCT16 -> threshold+nnz -> second DK apply (ref bug) ----
    int jb = t >> 6;
    int p  = t & 63;
    float h[16];
    {
        float g[16], gt[16];
        if (jb < nb) {
#pragma unroll
            for (int k = 0; k < 16; k++) g[k] = nbT[selOff[jb][k] + p];
            int cnt = 0;
#pragma unroll
            for (int l = 0; l < 16; l++) {
                float acc = 0.f;
#pragma unroll
                for (int k = 0; k < 16; k++) acc += sDK[l * 16 + k] * g[k];
                bool m = fabsf(acc) > 0.135f;
                cnt += m ? 1 : 0;
                gt[l] = m ? acc : 0.0f;
            }
            int wsum = __reduce_add_sync(0xffffffffu, cnt);
            if (lane == 0) atomicAdd(&snnz[jb], wsum);
#pragma unroll
            for (int l = 0; l < 16; l++) {
                float acc = 0.f;
#pragma unroll
                for (int k = 0; k < 16; k++) acc += sDK[l * 16 + k] * gt[k];
                h[l] = acc;
            }
        }
    }
    __syncthreads();   // [4] all nbT reads done -> safe to overwrite via GB alias
    if (jb < nb) {
#pragma unroll
        for (int l = 0; l < 16; l++) GB[(jb * 16 + l) * RP + p] = h[l];
    }
    __syncthreads();   // [5]

    // ---- 2D inverse (registers) fused with weighted float4 scatter ----
    if (jb < nb) {
        int r  = t & 63;
        int k  = r >> 2;
        int yp = r & 3;
        int y0 = yp * 2, y1 = y0 + 1;
        float wgt = 400.0f / fmaxf((float)snnz[jb], 1.0f);
        const float* gk = &GB[(jb * 16 + k) * RP];
        float tmp0[8], tmp1[8];
#pragma unroll
        for (int a = 0; a < 8; a++) {
            float4 v0 = *(const float4*)(gk + a * 8);
            float4 v1 = *(const float4*)(gk + a * 8 + 4);
            tmp0[a] = v0.x * sD[0 * 8 + y0] + v0.y * sD[1 * 8 + y0] +
                      v0.z * sD[2 * 8 + y0] + v0.w * sD[3 * 8 + y0] +
                      v1.x * sD[4 * 8 + y0] + v1.y * sD[5 * 8 + y0] +
                      v1.z * sD[6 * 8 + y0] + v1.w * sD[7 * 8 + y0];
            tmp1[a] = v0.x * sD[0 * 8 + y1] + v0.y * sD[1 * 8 + y1] +
                      v0.z * sD[2 * 8 + y1] + v0.w * sD[3 * 8 + y1] +
                      v1.x * sD[4 * 8 + y1] + v1.y * sD[5 * 8 + y1] +
                      v1.z * sD[6 * 8 + y1] + v1.w * sD[7 * 8 + y1];
        }
        int baseRow = selYs[jb][k];
        int baseCol = selXs[jb][k] + y0;
#pragma unroll
        for (int b = 0; b < 8; b++) {
            float o0 = 0.f, o1 = 0.f;
#pragma unroll
            for (int a = 0; a < 8; a++) {
                float dv = sD[a * 8 + b];
                o0 += dv * tmp0[a];
                o1 += dv * tmp1[a];
            }
            float4 v = make_float4(wgt * o0, wgt, wgt * o1, wgt);
            atomicAdd((float4*)(ncImg + ((baseRow + b) * WW + baseCol) * 2), v);
        }
    }
}

// ---------------------------------------------------------------------------
__global__ void div_kernel(float* __restrict__ out) {
    int idx = blockIdx.x * blockDim.x + threadIdx.x;
    float2 v = ((float2*)g_nc)[idx];
    out[idx] = v.x / fmaxf(v.y, 1e-8f);
}

// ---------------------------------------------------------------------------
extern "C" void kernel_launch(void* const* d_in, const int* in_sizes, int n_in,
                              void* d_out, int out_size) {
    const float* x = (const float*)d_in[0];
    (void)in_sizes; (void)n_in; (void)out_size;

    zero_kernel<<<1024, 256>>>();
    dct_kernel<<<(NIMG * NBLK * NBLK + 3) / 4, 256>>>(x);
    bm3d_kernel<<<dim3(16, NBLK, NIMG), 256>>>();
    div_kernel<<<2048, 256>>>((float*)d_out);
}

// round 6
// speedup vs baseline: 1.6559x; 1.6559x over previous
#include <cuda_runtime.h>

#define HH 256
#define WW 256
#define NBLK 63
#define CAND 81
#define KSEL 16
#define NIMG 8
#define RP 68   // padded nbT row stride (floats): kills 4-way LDS conflicts

__device__ __align__(16) float g_T[NIMG * NBLK * NBLK * 64];
__device__ __align__(16) float g_nc[NIMG * HH * WW * 2];

// ---------------------------------------------------------------------------
__global__ void zero_kernel() {
    int idx = blockIdx.x * blockDim.x + threadIdx.x;
    ((float4*)g_nc)[idx] = make_float4(0.f, 0.f, 0.f, 0.f);
}

// ---------------------------------------------------------------------------
// 8x8 DCT of every patch
// ---------------------------------------------------------------------------
__global__ void dct_kernel(const float* __restrict__ x) {
    __shared__ float sD[64];
    __shared__ float sp[4][64];
    __shared__ float st[4][64];
    int t = threadIdx.x;
    if (t < 64) {
        int k = t >> 3, i = t & 7;
        float v = cospif((float)((2 * i + 1) * k) / 16.0f) * 0.5f;
        if (k == 0) v = 0.35355339059327373f;
        sD[t] = v;
    }
    int grp = t >> 6;
    int lt = t & 63;
    int pid = blockIdx.x * 4 + grp;
    bool valid = pid < NIMG * NBLK * NBLK;
    int img = 0, bi = 0, bj = 0;
    if (valid) {
        img = pid / (NBLK * NBLK);
        int r = pid % (NBLK * NBLK);
        bi = r / NBLK; bj = r % NBLK;
    }
    __syncthreads();
    if (valid) {
        int b = lt >> 3, c = lt & 7;
        float v = x[img * (HH * WW) + (bi * 4 + b) * WW + (bj * 4 + c)];
        sp[grp][lt] = fminf(fmaxf(v, 0.0f), 1.0f);
    }
    __syncthreads();
    if (valid) {
        int a = lt >> 3, c = lt & 7;
        float acc = 0.f;
#pragma unroll
        for (int b = 0; b < 8; b++) acc += sD[a * 8 + b] * sp[grp][b * 8 + c];
        st[grp][lt] = acc;
    }
    __syncthreads();
    if (valid) {
        int a = lt >> 3, d = lt & 7;
        float acc = 0.f;
#pragma unroll
        for (int c = 0; c < 8; c++) acc += st[grp][a * 8 + c] * sD[d * 8 + c];
        g_T[pid * 64 + lt] = acc;
    }
}

// ---------------------------------------------------------------------------
// Main pipeline (R1 structure: 128 threads, serial 4 jb).
// Changes vs R1: grid remap (img fastest -> low atomic contention),
// 8-lane distance reduction, padded nbT rows.
// ---------------------------------------------------------------------------
__global__ void __launch_bounds__(128) bm3d_kernel() {
    __shared__ float nbT[9 * 12 * RP];      // 29376 B (padded rows)
    __shared__ float GA[16 * 64];
    __shared__ float GB[16 * 64];
    __shared__ float sDK[256];
    __shared__ float sD[64];
    __shared__ float sdist[CAND];
    __shared__ int selOff[KSEL];
    __shared__ int selYs[KSEL];
    __shared__ int selXs[KSEL];
    __shared__ int snnz;

    int t = threadIdx.x;
    int img = blockIdx.x;              // fastest -> co-resident CTAs on different images
    int j0 = blockIdx.y * 4;
    int i = blockIdx.z;
    int nb = min(4, NBLK - j0);

    if (t < 64) {
        int k = t >> 3, ii = t & 7;
        float v = cospif((float)((2 * ii + 1) * k) / 16.0f) * 0.5f;
        if (k == 0) v = 0.35355339059327373f;
        sD[t] = v;
    }
    for (int u = t; u < 256; u += 128) {
        int k = u >> 4, ii = u & 15;
        float v = cospif((float)((2 * ii + 1) * k) / 32.0f) * 0.35355339059327373f;
        if (k == 0) v = 0.25f;
        sDK[u] = v;
    }
    const float* Timg = g_T + img * (NBLK * NBLK * 64);
    for (int idx = t; idx < 9 * 12 * 64; idx += 128) {
        int r = idx / (12 * 64);
        int s = (idx >> 6) % 12;
        int p = idx & 63;
        int ci = min(max(i - 4 + r, 0), NBLK - 1);
        int cj = min(max(j0 - 4 + s, 0), NBLK - 1);
        nbT[(r * 12 + s) * RP + p] = Timg[(ci * NBLK + cj) * 64 + p];
    }
    __syncthreads();

    int lane = t & 31, warp = t >> 5;
    int grpL = lane >> 3;              // 0..3
    int sub  = lane & 7;               // 0..7
    float* ncImg = g_nc + img * (HH * WW * 2);

    for (int jb = 0; jb < nb; jb++) {
        int j = j0 + jb;
        if (t == 0) snnz = 0;

        // --- candidate distances: 8-lane groups, 16 candidates/iter over CTA ---
        {
            const float* rp = &nbT[(4 * 12 + jb + 4) * RP + sub * 8];
            for (int cb = warp * 4; cb < CAND; cb += 16) {
                int cid = min(cb + grpL, CAND - 1);
                int rr = cid / 9;
                int sc = jb + (cid % 9);
                const float* cp = &nbT[(rr * 12 + sc) * RP + sub * 8];
                float acc = 0.f;
#pragma unroll
                for (int q = 0; q < 4; q++) {
                    float2 cv = *(const float2*)(cp + q * 2);
                    float2 rv = *(const float2*)(rp + q * 2);
                    float d0 = cv.x - rv.x, d1 = cv.y - rv.y;
                    acc += d0 * d0 + d1 * d1;
                }
                acc += __shfl_xor_sync(0xffffffffu, acc, 1);
                acc += __shfl_xor_sync(0xffffffffu, acc, 2);
                acc += __shfl_xor_sync(0xffffffffu, acc, 4);
                if (sub == 0 && cb + grpL < CAND) sdist[cid] = acc;
            }
        }
        __syncthreads();

        // --- rank-based top-16, ties -> lower candidate index (JAX top_k) ---
        if (t < CAND) {
            float my = sdist[t];
            int rank = 0;
            for (int c = 0; c < CAND; c++) {
                float dc = sdist[c];
                rank += (dc < my) || (dc == my && c < t);
            }
            if (rank < KSEL) {
                int rr = t / 9;
                int dx = t % 9;
                selOff[rank] = (rr * 12 + jb + dx) * RP;
                int ci = min(max(i - 4 + rr, 0), NBLK - 1);
                int cj = min(max(j - 4 + dx, 0), NBLK - 1);
                selYs[rank] = ci * 4;
                selXs[rank] = cj * 4;
            }
        }
        __syncthreads();

        // --- forward 16-pt DCT along group axis + hard threshold + nnz ---
        {
            int p = t & 63, half = t >> 6;
            float g[16];
#pragma unroll
            for (int k = 0; k < 16; k++) g[k] = nbT[selOff[k] + p];
            int cnt = 0;
#pragma unroll
            for (int q = 0; q < 8; q++) {
                int l = half * 8 + q;
                float acc = 0.f;
#pragma unroll
                for (int k = 0; k < 16; k++) acc += sDK[l * 16 + k] * g[k];
                bool m = fabsf(acc) > 0.135f;
                cnt += m ? 1 : 0;
                GA[l * 64 + p] = m ? acc : 0.0f;
            }
            atomicAdd(&snnz, cnt);
        }
        __syncthreads();
        float wgt = 400.0f / fmaxf((float)snnz, 1.0f);

        // --- "inverse" along group axis: reference applies DK AGAIN (not DK^T) ---
        {
            int p = t & 63, half = t >> 6;
            float g[16];
#pragma unroll
            for (int k = 0; k < 16; k++) g[k] = GA[k * 64 + p];
#pragma unroll
            for (int q = 0; q < 8; q++) {
                int l = half * 8 + q;
                float acc = 0.f;
#pragma unroll
                for (int k = 0; k < 16; k++) acc += sDK[l * 16 + k] * g[k];
                GB[l * 64 + p] = acc;
            }
        }
        __syncthreads();

        // --- 2D inverse stage 1: tmp[a][y] = sum_d G[a][d] * D[d][y] ---
        {
            int p = t & 63, half = t >> 6;
            int a = p >> 3, y = p & 7;
#pragma unroll
            for (int q = 0; q < 8; q++) {
                int k = half * 8 + q;
                float acc = 0.f;
#pragma unroll
                for (int d = 0; d < 8; d++) acc += GB[k * 64 + a * 8 + d] * sD[d * 8 + y];
                GA[k * 64 + p] = acc;
            }
        }
        __syncthreads();

        // --- 2D inverse stage 2 fused with weighted scatter (float4 atomics) ---
        {
            for (int item = t; item < 512; item += 128) {
                int k = item >> 5;
                int rem = item & 31;
                int b = rem >> 2;           // output patch row
                int cp2 = (rem & 3) * 2;    // even output column within patch
                float a0 = 0.f, a1 = 0.f;
#pragma unroll
                for (int a = 0; a < 8; a++) {
                    float dv = sD[a * 8 + b];
                    a0 += dv * GA[k * 64 + a * 8 + cp2];
                    a1 += dv * GA[k * 64 + a * 8 + cp2 + 1];
                }
                int row = selYs[k] + b;
                int col = selXs[k] + cp2;
                float4 v = make_float4(wgt * a0, wgt, wgt * a1, wgt);
                atomicAdd((float4*)(ncImg + (row * WW + col) * 2), v);
            }
        }
        __syncthreads();
    }
}

// ---------------------------------------------------------------------------
__global__ void div_kernel(float* __restrict__ out) {
    int idx = blockIdx.x * blockDim.x + threadIdx.x;
    float2 v = ((float2*)g_nc)[idx];
    out[idx] = v.x / fmaxf(v.y, 1e-8f);
}

// ---------------------------------------------------------------------------
extern "C" void kernel_launch(void* const* d_in, const int* in_sizes, int n_in,
                              void* d_out, int out_size) {
    const float* x = (const float*)d_in[0];
    (void)in_sizes; (void)n_in; (void)out_size;

    zero_kernel<<<1024, 256>>>();
    dct_kernel<<<(NIMG * NBLK * NBLK + 3) / 4, 256>>>(x);
    bm3d_kernel<<<dim3(NIMG, 16, NBLK), 128>>>();
    div_kernel<<<2048, 256>>>((float*)d_out);
}

// round 7
// speedup vs baseline: 1.7395x; 1.0505x over previous
#include <cuda_runtime.h>

#define HH 256
#define WW 256
#define NBLK 63
#define CAND 81
#define KSEL 16
#define NIMG 8
#define RP 68   // padded nbT row stride (floats)

__device__ __align__(16) float g_T[NIMG * NBLK * NBLK * 64];
__device__ __align__(16) float g_nc[NIMG * HH * WW * 2];

// ---------------------------------------------------------------------------
__global__ void zero_kernel() {
    int idx = blockIdx.x * blockDim.x + threadIdx.x;
    ((float4*)g_nc)[idx] = make_float4(0.f, 0.f, 0.f, 0.f);
}

// ---------------------------------------------------------------------------
// 8x8 DCT of every patch
// ---------------------------------------------------------------------------
__global__ void dct_kernel(const float* __restrict__ x) {
    __shared__ float sD[64];
    __shared__ float sp[4][64];
    __shared__ float st[4][64];
    int t = threadIdx.x;
    if (t < 64) {
        int k = t >> 3, i = t & 7;
        float v = cospif((float)((2 * i + 1) * k) / 16.0f) * 0.5f;
        if (k == 0) v = 0.35355339059327373f;
        sD[t] = v;
    }
    int grp = t >> 6;
    int lt = t & 63;
    int pid = blockIdx.x * 4 + grp;
    bool valid = pid < NIMG * NBLK * NBLK;
    int img = 0, bi = 0, bj = 0;
    if (valid) {
        img = pid / (NBLK * NBLK);
        int r = pid % (NBLK * NBLK);
        bi = r / NBLK; bj = r % NBLK;
    }
    __syncthreads();
    if (valid) {
        int b = lt >> 3, c = lt & 7;
        float v = x[img * (HH * WW) + (bi * 4 + b) * WW + (bj * 4 + c)];
        sp[grp][lt] = fminf(fmaxf(v, 0.0f), 1.0f);
    }
    __syncthreads();
    if (valid) {
        int a = lt >> 3, c = lt & 7;
        float acc = 0.f;
#pragma unroll
        for (int b = 0; b < 8; b++) acc += sD[a * 8 + b] * sp[grp][b * 8 + c];
        st[grp][lt] = acc;
    }
    __syncthreads();
    if (valid) {
        int a = lt >> 3, d = lt & 7;
        float acc = 0.f;
#pragma unroll
        for (int c = 0; c < 8; c++) acc += st[grp][a * 8 + c] * sD[d * 8 + c];
        g_T[pid * 64 + lt] = acc;
    }
}

// ---------------------------------------------------------------------------
// Main pipeline: 256 threads = two independent 128-thread halves, each
// running the staged R6 pipeline on its own jb block. 12 barriers/CTA.
// smem = 48080 B (< 48KB static cap).
// ---------------------------------------------------------------------------
__global__ void __launch_bounds__(256) bm3d_kernel() {
    __shared__ float nbT[9 * 12 * RP];          // 29376 B (shared by both halves)
    __shared__ float GA[2][16 * 64];            // 8192 B
    __shared__ float GB[2][16 * 64];            // 8192 B
    __shared__ float sDK[256];
    __shared__ float sD[64];
    __shared__ float sdist[2][CAND];
    __shared__ int selOff[2][KSEL];
    __shared__ int selYs[2][KSEL];
    __shared__ int selXs[2][KSEL];
    __shared__ int snnz[2];

    int t = threadIdx.x;
    int img = blockIdx.x;              // fastest -> co-resident CTAs on different images
    int j0 = blockIdx.y * 4;
    int i = blockIdx.z;
    int nb = min(4, NBLK - j0);

    int half = t >> 7;                 // 0/1
    int ht   = t & 127;                // thread within half
    int lane = t & 31;
    int hwarp = ht >> 5;               // warp within half (0..3)
    int grpL = lane >> 3;
    int sub  = lane & 7;

    {   // DCT-16 matrix: one entry per thread
        int k = t >> 4, ii = t & 15;
        float v = cospif((float)((2 * ii + 1) * k) / 32.0f) * 0.35355339059327373f;
        if (k == 0) v = 0.25f;
        sDK[t] = v;
    }
    if (t < 64) {
        int k = t >> 3, ii = t & 7;
        float v = cospif((float)((2 * ii + 1) * k) / 16.0f) * 0.5f;
        if (k == 0) v = 0.35355339059327373f;
        sD[t] = v;
    }

    const float* Timg = g_T + img * (NBLK * NBLK * 64);
    for (int idx = t; idx < 9 * 12 * 64; idx += 256) {
        int r = idx / (12 * 64);
        int s = (idx >> 6) % 12;
        int p = idx & 63;
        int ci = min(max(i - 4 + r, 0), NBLK - 1);
        int cj = min(max(j0 - 4 + s, 0), NBLK - 1);
        nbT[(r * 12 + s) * RP + p] = Timg[(ci * NBLK + cj) * 64 + p];
    }
    __syncthreads();

    float* ncImg = g_nc + img * (HH * WW * 2);

    for (int jp = 0; jp < 2; jp++) {
        int jb = jp * 2 + half;
        bool active = jb < nb;
        int j = j0 + jb;
        if (ht == 0) snnz[half] = 0;

        // --- candidate distances: 8-lane groups, 16 cands/iter per half ---
        if (active) {
            const float* rp = &nbT[(4 * 12 + jb + 4) * RP + sub * 8];
            for (int cb = hwarp * 4; cb < CAND; cb += 16) {
                int cid = min(cb + grpL, CAND - 1);
                int rr = cid / 9;
                int sc = jb + (cid % 9);
                const float* cp = &nbT[(rr * 12 + sc) * RP + sub * 8];
                float acc = 0.f;
#pragma unroll
                for (int q = 0; q < 4; q++) {
                    float2 cv = *(const float2*)(cp + q * 2);
                    float2 rv = *(const float2*)(rp + q * 2);
                    float d0 = cv.x - rv.x, d1 = cv.y - rv.y;
                    acc += d0 * d0 + d1 * d1;
                }
                acc += __shfl_xor_sync(0xffffffffu, acc, 1);
                acc += __shfl_xor_sync(0xffffffffu, acc, 2);
                acc += __shfl_xor_sync(0xffffffffu, acc, 4);
                if (sub == 0 && cb + grpL < CAND) sdist[half][cid] = acc;
            }
        }
        __syncthreads();

        // --- rank-based top-16, ties -> lower candidate index (JAX top_k) ---
        if (active && ht < CAND) {
            const float* ds = sdist[half];
            float my = ds[ht];
            int rank = 0;
            for (int c = 0; c < CAND; c++) {
                float dc = ds[c];
                rank += (dc < my) || (dc == my && c < ht);
            }
            if (rank < KSEL) {
                int rr = ht / 9;
                int dx = ht % 9;
                selOff[half][rank] = (rr * 12 + jb + dx) * RP;
                int ci = min(max(i - 4 + rr, 0), NBLK - 1);
                int cj = min(max(j - 4 + dx, 0), NBLK - 1);
                selYs[half][rank] = ci * 4;
                selXs[half][rank] = cj * 4;
            }
        }
        __syncthreads();

        // --- forward 16-pt DCT along group axis + hard threshold + nnz ---
        if (active) {
            int p = ht & 63, hh = ht >> 6;
            float g[16];
#pragma unroll
            for (int k = 0; k < 16; k++) g[k] = nbT[selOff[half][k] + p];
            int cnt = 0;
#pragma unroll
            for (int q = 0; q < 8; q++) {
                int l = hh * 8 + q;
                float acc = 0.f;
#pragma unroll
                for (int k = 0; k < 16; k++) acc += sDK[l * 16 + k] * g[k];
                bool m = fabsf(acc) > 0.135f;
                cnt += m ? 1 : 0;
                GA[half][l * 64 + p] = m ? acc : 0.0f;
            }
            atomicAdd(&snnz[half], cnt);
        }
        __syncthreads();
        float wgt = 400.0f / fmaxf((float)snnz[half], 1.0f);

        // --- "inverse" along group axis: reference applies DK AGAIN (not DK^T) ---
        if (active) {
            int p = ht & 63, hh = ht >> 6;
            float g[16];
#pragma unroll
            for (int k = 0; k < 16; k++) g[k] = GA[half][k * 64 + p];
#pragma unroll
            for (int q = 0; q < 8; q++) {
                int l = hh * 8 + q;
                float acc = 0.f;
#pragma unroll
                for (int k = 0; k < 16; k++) acc += sDK[l * 16 + k] * g[k];
                GB[half][l * 64 + p] = acc;
            }
        }
        __syncthreads();

        // --- 2D inverse stage 1: tmp[a][y] = sum_d G[a][d] * D[d][y] ---
        if (active) {
            int p = ht & 63, hh = ht >> 6;
            int a = p >> 3, y = p & 7;
#pragma unroll
            for (int q = 0; q < 8; q++) {
                int k = hh * 8 + q;
                float acc = 0.f;
#pragma unroll
                for (int d = 0; d < 8; d++) acc += GB[half][k * 64 + a * 8 + d] * sD[d * 8 + y];
                GA[half][k * 64 + p] = acc;
            }
        }
        __syncthreads();

        // --- 2D inverse stage 2 fused with weighted scatter (float4 atomics) ---
        if (active) {
            for (int item = ht; item < 512; item += 128) {
                int k = item >> 5;
                int rem = item & 31;
                int b = rem >> 2;
                int cp2 = (rem & 3) * 2;
                float a0 = 0.f, a1 = 0.f;
#pragma unroll
                for (int a = 0; a < 8; a++) {
                    float dv = sD[a * 8 + b];
                    a0 += dv * GA[half][k * 64 + a * 8 + cp2];
                    a1 += dv * GA[half][k * 64 + a * 8 + cp2 + 1];
                }
                int row = selYs[half][k] + b;
                int col = selXs[half][k] + cp2;
                float4 v = make_float4(wgt * a0, wgt, wgt * a1, wgt);
                atomicAdd((float4*)(ncImg + (row * WW + col) * 2), v);
            }
        }
        __syncthreads();
    }
}

// ---------------------------------------------------------------------------
__global__ void div_kernel(float* __restrict__ out) {
    int idx = blockIdx.x * blockDim.x + threadIdx.x;
    float2 v = ((float2*)g_nc)[idx];
    out[idx] = v.x / fmaxf(v.y, 1e-8f);
}

// ---------------------------------------------------------------------------
extern "C" void kernel_launch(void* const* d_in, const int* in_sizes, int n_in,
                              void* d_out, int out_size) {
    const float* x = (const float*)d_in[0];
    (void)in_sizes; (void)n_in; (void)out_size;

    zero_kernel<<<1024, 256>>>();
    dct_kernel<<<(NIMG * NBLK * NBLK + 3) / 4, 256>>>(x);
    bm3d_kernel<<<dim3(NIMG, 16, NBLK), 256>>>();
    div_kernel<<<2048, 256>>>((float*)d_out);
}

// round 9
// speedup vs baseline: 1.7961x; 1.0326x over previous
#include <cuda_runtime.h>

#define HH 256
#define WW 256
#define NBLK 63
#define CAND 81
#define KSEL 16
#define NIMG 8
#define RP 68   // padded nbT row stride (floats)

__device__ __align__(16) float g_T[NIMG * NBLK * NBLK * 64];
__device__ __align__(16) float g_nc[NIMG * HH * WW * 2];

// ---------------------------------------------------------------------------
// Compile-time DCT matrices -> FFMA immediates (no smem/const traffic).
// COS32(m) = cos(pi*m/32), float64-accurate literals rounded to fp32.
// ---------------------------------------------------------------------------
__device__ __host__ constexpr float COS32(int m) {
    m &= 63;
    if (m > 32) m = 64 - m;                  // cos symmetry: c(64-m)=c(m)
    bool neg = false;
    if (m > 16) { neg = true; m = 32 - m; }  // c(m) = -c(32-m)
    float v = 0.0f;
    switch (m) {
        case 0:  v = 1.0f; break;
        case 1:  v = 0.99518472667219693f; break;
        case 2:  v = 0.98078528040323044f; break;
        case 3:  v = 0.95694033573220882f; break;
        case 4:  v = 0.92387953251128674f; break;
        case 5:  v = 0.88192126434835505f; break;
        case 6:  v = 0.83146961230254524f; break;
        case 7:  v = 0.77301045336273699f; break;
        case 8:  v = 0.70710678118654752f; break;
        case 9:  v = 0.63439328416364549f; break;
        case 10: v = 0.55557023301960218f; break;
        case 11: v = 0.47139673682599764f; break;
        case 12: v = 0.38268343236508984f; break;
        case 13: v = 0.29028467725446233f; break;
        case 14: v = 0.19509032201612828f; break;
        case 15: v = 0.09801714032956077f; break;
        default: v = 0.0f; break;            // m == 16
    }
    return neg ? -v : v;
}
// DCT-16: row k, col i (row 0 = 1/4)
__device__ __host__ constexpr float DKc(int k, int i) {
    return (k == 0) ? 0.25f : 0.35355339059327373f * COS32((2 * i + 1) * k);
}
// DCT-8: row k, col i (row 0 = 1/sqrt(8));  cos(pi*m/16) = COS32(2m)
__device__ __host__ constexpr float D8c(int k, int i) {
    return (k == 0) ? 0.35355339059327373f : 0.5f * COS32(2 * (2 * i + 1) * k);
}

// ---------------------------------------------------------------------------
__global__ void zero_kernel() {
    int idx = blockIdx.x * blockDim.x + threadIdx.x;
    ((float4*)g_nc)[idx] = make_float4(0.f, 0.f, 0.f, 0.f);
}

// ---------------------------------------------------------------------------
// 8x8 DCT of every patch
// ---------------------------------------------------------------------------
__global__ void dct_kernel(const float* __restrict__ x) {
    __shared__ float sD[64];
    __shared__ float sp[4][64];
    __shared__ float st[4][64];
    int t = threadIdx.x;
    if (t < 64) {
        int k = t >> 3, i = t & 7;
        float v = cospif((float)((2 * i + 1) * k) / 16.0f) * 0.5f;
        if (k == 0) v = 0.35355339059327373f;
        sD[t] = v;
    }
    int grp = t >> 6;
    int lt = t & 63;
    int pid = blockIdx.x * 4 + grp;
    bool valid = pid < NIMG * NBLK * NBLK;
    int img = 0, bi = 0, bj = 0;
    if (valid) {
        img = pid / (NBLK * NBLK);
        int r = pid % (NBLK * NBLK);
        bi = r / NBLK; bj = r % NBLK;
    }
    __syncthreads();
    if (valid) {
        int b = lt >> 3, c = lt & 7;
        float v = x[img * (HH * WW) + (bi * 4 + b) * WW + (bj * 4 + c)];
        sp[grp][lt] = fminf(fmaxf(v, 0.0f), 1.0f);
    }
    __syncthreads();
    if (valid) {
        int a = lt >> 3, c = lt & 7;
        float acc = 0.f;
#pragma unroll
        for (int b = 0; b < 8; b++) acc += sD[a * 8 + b] * sp[grp][b * 8 + c];
        st[grp][lt] = acc;
    }
    __syncthreads();
    if (valid) {
        int a = lt >> 3, d = lt & 7;
        float acc = 0.f;
#pragma unroll
        for (int c = 0; c < 8; c++) acc += st[grp][a * 8 + c] * sD[d * 8 + c];
        g_T[pid * 64 + lt] = acc;
    }
}

// ---------------------------------------------------------------------------
// Main pipeline: 256 threads = two independent 128-thread halves.
// Group-axis DCT16 stages use compile-time immediates (FFMA-imm, zero LDS).
// ---------------------------------------------------------------------------
__global__ void __launch_bounds__(256) bm3d_kernel() {
    __shared__ float nbT[9 * 12 * RP];          // 29376 B
    __shared__ float GA[2][16 * 64];            // 8192 B
    __shared__ float GB[2][16 * 64];            // 8192 B
    __shared__ float sD[64];
    __shared__ float sdist[2][CAND];
    __shared__ int selOff[2][KSEL];
    __shared__ int selYs[2][KSEL];
    __shared__ int selXs[2][KSEL];
    __shared__ int snnz[2];

    int t = threadIdx.x;
    int img = blockIdx.x;
    int j0 = blockIdx.y * 4;
    int i = blockIdx.z;
    int nb = min(4, NBLK - j0);

    int half = t >> 7;
    int ht   = t & 127;
    int lane = t & 31;
    int hwarp = ht >> 5;
    int grpL = lane >> 3;
    int sub  = lane & 7;

    if (t < 64) {
        int k = t >> 3, ii = t & 7;
        sD[t] = D8c(k, ii);
    }

    const float* Timg = g_T + img * (NBLK * NBLK * 64);
    for (int idx = t; idx < 9 * 12 * 64; idx += 256) {
        int r = idx / (12 * 64);
        int s = (idx >> 6) % 12;
        int p = idx & 63;
        int ci = min(max(i - 4 + r, 0), NBLK - 1);
        int cj = min(max(j0 - 4 + s, 0), NBLK - 1);
        nbT[(r * 12 + s) * RP + p] = Timg[(ci * NBLK + cj) * 64 + p];
    }
    __syncthreads();

    float* ncImg = g_nc + img * (HH * WW * 2);

    for (int jp = 0; jp < 2; jp++) {
        int jb = jp * 2 + half;
        bool active = jb < nb;
        int j = j0 + jb;
        if (ht == 0) snnz[half] = 0;

        // --- candidate distances: 8-lane groups ---
        if (active) {
            const float* rp = &nbT[(4 * 12 + jb + 4) * RP + sub * 8];
            for (int cb = hwarp * 4; cb < CAND; cb += 16) {
                int cid = min(cb + grpL, CAND - 1);
                int rr = cid / 9;
                int sc = jb + (cid % 9);
                const float* cp = &nbT[(rr * 12 + sc) * RP + sub * 8];
                float acc = 0.f;
#pragma unroll
                for (int q = 0; q < 4; q++) {
                    float2 cv = *(const float2*)(cp + q * 2);
                    float2 rv = *(const float2*)(rp + q * 2);
                    float d0 = cv.x - rv.x, d1 = cv.y - rv.y;
                    acc += d0 * d0 + d1 * d1;
                }
                acc += __shfl_xor_sync(0xffffffffu, acc, 1);
                acc += __shfl_xor_sync(0xffffffffu, acc, 2);
                acc += __shfl_xor_sync(0xffffffffu, acc, 4);
                if (sub == 0 && cb + grpL < CAND) sdist[half][cid] = acc;
            }
        }
        __syncthreads();

        // --- rank-based top-16, ties -> lower candidate index ---
        if (active && ht < CAND) {
            const float* ds = sdist[half];
            float my = ds[ht];
            int rank = 0;
            for (int c = 0; c < CAND; c++) {
                float dc = ds[c];
                rank += (dc < my) || (dc == my && c < ht);
            }
            if (rank < KSEL) {
                int rr = ht / 9;
                int dx = ht % 9;
                selOff[half][rank] = (rr * 12 + jb + dx) * RP;
                int ci = min(max(i - 4 + rr, 0), NBLK - 1);
                int cj = min(max(j - 4 + dx, 0), NBLK - 1);
                selYs[half][rank] = ci * 4;
                selXs[half][rank] = cj * 4;
            }
        }
        __syncthreads();

        // --- forward DCT16 (immediates) + threshold + nnz ---
        if (active) {
            int p = ht & 63;
            float g[16];
#pragma unroll
            for (int k = 0; k < 16; k++) g[k] = nbT[selOff[half][k] + p];
            int cnt = 0;
            if (ht < 64) {
#pragma unroll
                for (int q = 0; q < 8; q++) {
                    float acc = 0.f;
#pragma unroll
                    for (int k = 0; k < 16; k++) acc += DKc(q, k) * g[k];
                    bool m = fabsf(acc) > 0.135f;
                    cnt += m ? 1 : 0;
                    GA[half][q * 64 + p] = m ? acc : 0.0f;
                }
            } else {
#pragma unroll
                for (int q = 8; q < 16; q++) {
                    float acc = 0.f;
#pragma unroll
                    for (int k = 0; k < 16; k++) acc += DKc(q, k) * g[k];
                    bool m = fabsf(acc) > 0.135f;
                    cnt += m ? 1 : 0;
                    GA[half][q * 64 + p] = m ? acc : 0.0f;
                }
            }
            cnt = __reduce_add_sync(0xffffffffu, cnt);
            if (lane == 0) atomicAdd(&snnz[half], cnt);
        }
        __syncthreads();
        float wgt = 400.0f / fmaxf((float)snnz[half], 1.0f);

        // --- "inverse" along group axis: DK applied AGAIN (ref bug), immediates ---
        if (active) {
            int p = ht & 63;
            float g[16];
#pragma unroll
            for (int k = 0; k < 16; k++) g[k] = GA[half][k * 64 + p];
            if (ht < 64) {
#pragma unroll
                for (int q = 0; q < 8; q++) {
                    float acc = 0.f;
#pragma unroll
                    for (int k = 0; k < 16; k++) acc += DKc(q, k) * g[k];
                    GB[half][q * 64 + p] = acc;
                }
            } else {
#pragma unroll
                for (int q = 8; q < 16; q++) {
                    float acc = 0.f;
#pragma unroll
                    for (int k = 0; k < 16; k++) acc += DKc(q, k) * g[k];
                    GB[half][q * 64 + p] = acc;
                }
            }
        }
        __syncthreads();

        // --- 2D inverse stage 1: tmp[a][y] = sum_d G[a][d] * D[d][y] ---
        if (active) {
            int p = ht & 63, hh = ht >> 6;
            int a = p >> 3, y = p & 7;
#pragma unroll
            for (int q = 0; q < 8; q++) {
                int k = hh * 8 + q;
                float acc = 0.f;
#pragma unroll
                for (int d = 0; d < 8; d++) acc += GB[half][k * 64 + a * 8 + d] * sD[d * 8 + y];
                GA[half][k * 64 + p] = acc;
            }
        }
        __syncthreads();

        // --- 2D inverse stage 2 fused with weighted scatter (float4 REDs) ---
        if (active) {
            for (int item = ht; item < 512; item += 128) {
                int k = item >> 5;
                int rem = item & 31;
                int b = rem >> 2;
                int cp2 = (rem & 3) * 2;
                float a0 = 0.f, a1 = 0.f;
#pragma unroll
                for (int a = 0; a < 8; a++) {
                    float dv = sD[a * 8 + b];
                    a0 += dv * GA[half][k * 64 + a * 8 + cp2];
                    a1 += dv * GA[half][k * 64 + a * 8 + cp2 + 1];
                }
                int row = selYs[half][k] + b;
                int col = selXs[half][k] + cp2;
                float4 v = make_float4(wgt * a0, wgt, wgt * a1, wgt);
                atomicAdd((float4*)(ncImg + (row * WW + col) * 2), v);
            }
        }
        __syncthreads();
    }
}

// ---------------------------------------------------------------------------
__global__ void div_kernel(float* __restrict__ out) {
    int idx = blockIdx.x * blockDim.x + threadIdx.x;
    float2 v = ((float2*)g_nc)[idx];
    out[idx] = v.x / fmaxf(v.y, 1e-8f);
}

// ---------------------------------------------------------------------------
extern "C" void kernel_launch(void* const* d_in, const int* in_sizes, int n_in,
                              void* d_out, int out_size) {
    const float* x = (const float*)d_in[0];
    (void)in_sizes; (void)n_in; (void)out_size;

    zero_kernel<<<1024, 256>>>();
    dct_kernel<<<(NIMG * NBLK * NBLK + 3) / 4, 256>>>(x);
    bm3d_kernel<<<dim3(NIMG, 16, NBLK), 256>>>();
    div_kernel<<<2048, 256>>>((float*)d_out);
}

// round 10
// speedup vs baseline: 1.8070x; 1.0060x over previous
#include <cuda_runtime.h>

#define HH 256
#define WW 256
#define NBLK 63
#define CAND 81
#define KSEL 16
#define NIMG 8
#define RP 68   // padded nbT row stride (floats)

__device__ __align__(16) float g_T[NIMG * NBLK * NBLK * 64];
__device__ __align__(16) float g_num[NIMG * HH * WW];        // plain num accumulator
__device__ __align__(16) float g_W[NIMG * NBLK * NBLK];      // per-origin weight map

// ---------------------------------------------------------------------------
// Compile-time DCT matrices -> FFMA immediates.
// ---------------------------------------------------------------------------
__device__ __host__ constexpr float COS32(int m) {
    m &= 63;
    if (m > 32) m = 64 - m;
    bool neg = false;
    if (m > 16) { neg = true; m = 32 - m; }
    float v = 0.0f;
    switch (m) {
        case 0:  v = 1.0f; break;
        case 1:  v = 0.99518472667219693f; break;
        case 2:  v = 0.98078528040323044f; break;
        case 3:  v = 0.95694033573220882f; break;
        case 4:  v = 0.92387953251128674f; break;
        case 5:  v = 0.88192126434835505f; break;
        case 6:  v = 0.83146961230254524f; break;
        case 7:  v = 0.77301045336273699f; break;
        case 8:  v = 0.70710678118654752f; break;
        case 9:  v = 0.63439328416364549f; break;
        case 10: v = 0.55557023301960218f; break;
        case 11: v = 0.47139673682599764f; break;
        case 12: v = 0.38268343236508984f; break;
        case 13: v = 0.29028467725446233f; break;
        case 14: v = 0.19509032201612828f; break;
        case 15: v = 0.09801714032956077f; break;
        default: v = 0.0f; break;
    }
    return neg ? -v : v;
}
__device__ __host__ constexpr float DKc(int k, int i) {
    return (k == 0) ? 0.25f : 0.35355339059327373f * COS32((2 * i + 1) * k);
}
__device__ __host__ constexpr float D8c(int k, int i) {
    return (k == 0) ? 0.35355339059327373f : 0.5f * COS32(2 * (2 * i + 1) * k);
}

// ---------------------------------------------------------------------------
__global__ void zero_kernel() {
    int idx = blockIdx.x * blockDim.x + threadIdx.x;
    const int N_NUM4 = NIMG * HH * WW / 4;          // 131072
    const int N_W4   = NIMG * NBLK * NBLK / 4;      // 7938
    if (idx < N_NUM4)
        ((float4*)g_num)[idx] = make_float4(0.f, 0.f, 0.f, 0.f);
    else if (idx < N_NUM4 + N_W4)
        ((float4*)g_W)[idx - N_NUM4] = make_float4(0.f, 0.f, 0.f, 0.f);
}

__global__ void nop_kernel() {}

// ---------------------------------------------------------------------------
// 8x8 DCT of every patch
// ---------------------------------------------------------------------------
__global__ void dct_kernel(const float* __restrict__ x) {
    __shared__ float sD[64];
    __shared__ float sp[4][64];
    __shared__ float st[4][64];
    int t = threadIdx.x;
    if (t < 64) {
        int k = t >> 3, i = t & 7;
        sD[t] = D8c(k, i);
    }
    int grp = t >> 6;
    int lt = t & 63;
    int pid = blockIdx.x * 4 + grp;
    bool valid = pid < NIMG * NBLK * NBLK;
    int img = 0, bi = 0, bj = 0;
    if (valid) {
        img = pid / (NBLK * NBLK);
        int r = pid % (NBLK * NBLK);
        bi = r / NBLK; bj = r % NBLK;
    }
    __syncthreads();
    if (valid) {
        int b = lt >> 3, c = lt & 7;
        float v = x[img * (HH * WW) + (bi * 4 + b) * WW + (bj * 4 + c)];
        sp[grp][lt] = fminf(fmaxf(v, 0.0f), 1.0f);
    }
    __syncthreads();
    if (valid) {
        int a = lt >> 3, c = lt & 7;
        float acc = 0.f;
#pragma unroll
        for (int b = 0; b < 8; b++) acc += sD[a * 8 + b] * sp[grp][b * 8 + c];
        st[grp][lt] = acc;
    }
    __syncthreads();
    if (valid) {
        int a = lt >> 3, d = lt & 7;
        float acc = 0.f;
#pragma unroll
        for (int c = 0; c < 8; c++) acc += st[grp][a * 8 + c] * sD[d * 8 + c];
        g_T[pid * 64 + lt] = acc;
    }
}

// ---------------------------------------------------------------------------
// Main pipeline: 256 threads = two independent 128-thread halves.
// Scatter: num-only float4 quads (4 pixels/RED) + one scalar W RED per patch.
// ---------------------------------------------------------------------------
__global__ void __launch_bounds__(256) bm3d_kernel() {
    __shared__ float nbT[9 * 12 * RP];
    __shared__ float GA[2][16 * 64];
    __shared__ float GB[2][16 * 64];
    __shared__ float sD[64];
    __shared__ float sdist[2][CAND];
    __shared__ int selOff[2][KSEL];
    __shared__ int selYs[2][KSEL];
    __shared__ int selXs[2][KSEL];
    __shared__ int snnz[2];

    int t = threadIdx.x;
    int img = blockIdx.x;
    int j0 = blockIdx.y * 4;
    int i = blockIdx.z;
    int nb = min(4, NBLK - j0);

    int half = t >> 7;
    int ht   = t & 127;
    int lane = t & 31;
    int hwarp = ht >> 5;
    int grpL = lane >> 3;
    int sub  = lane & 7;

    if (t < 64) {
        int k = t >> 3, ii = t & 7;
        sD[t] = D8c(k, ii);
    }

    const float* Timg = g_T + img * (NBLK * NBLK * 64);
    for (int idx = t; idx < 9 * 12 * 64; idx += 256) {
        int r = idx / (12 * 64);
        int s = (idx >> 6) % 12;
        int p = idx & 63;
        int ci = min(max(i - 4 + r, 0), NBLK - 1);
        int cj = min(max(j0 - 4 + s, 0), NBLK - 1);
        nbT[(r * 12 + s) * RP + p] = Timg[(ci * NBLK + cj) * 64 + p];
    }
    __syncthreads();

    float* numImg = g_num + img * (HH * WW);
    float* Wimg   = g_W + img * (NBLK * NBLK);

    for (int jp = 0; jp < 2; jp++) {
        int jb = jp * 2 + half;
        bool active = jb < nb;
        int j = j0 + jb;
        if (ht == 0) snnz[half] = 0;

        // --- candidate distances: 8-lane groups ---
        if (active) {
            const float* rp = &nbT[(4 * 12 + jb + 4) * RP + sub * 8];
            for (int cb = hwarp * 4; cb < CAND; cb += 16) {
                int cid = min(cb + grpL, CAND - 1);
                int rr = cid / 9;
                int sc = jb + (cid % 9);
                const float* cp = &nbT[(rr * 12 + sc) * RP + sub * 8];
                float acc = 0.f;
#pragma unroll
                for (int q = 0; q < 4; q++) {
                    float2 cv = *(const float2*)(cp + q * 2);
                    float2 rv = *(const float2*)(rp + q * 2);
                    float d0 = cv.x - rv.x, d1 = cv.y - rv.y;
                    acc += d0 * d0 + d1 * d1;
                }
                acc += __shfl_xor_sync(0xffffffffu, acc, 1);
                acc += __shfl_xor_sync(0xffffffffu, acc, 2);
                acc += __shfl_xor_sync(0xffffffffu, acc, 4);
                if (sub == 0 && cb + grpL < CAND) sdist[half][cid] = acc;
            }
        }
        __syncthreads();

        // --- rank-based top-16, ties -> lower candidate index ---
        if (active && ht < CAND) {
            const float* ds = sdist[half];
            float my = ds[ht];
            int rank = 0;
            for (int c = 0; c < CAND; c++) {
                float dc = ds[c];
                rank += (dc < my) || (dc == my && c < ht);
            }
            if (rank < KSEL) {
                int rr = ht / 9;
                int dx = ht % 9;
                selOff[half][rank] = (rr * 12 + jb + dx) * RP;
                int ci = min(max(i - 4 + rr, 0), NBLK - 1);
                int cj = min(max(j - 4 + dx, 0), NBLK - 1);
                selYs[half][rank] = ci * 4;
                selXs[half][rank] = cj * 4;
            }
        }
        __syncthreads();

        // --- forward DCT16 (immediates) + threshold + nnz ---
        if (active) {
            int p = ht & 63;
            float g[16];
#pragma unroll
            for (int k = 0; k < 16; k++) g[k] = nbT[selOff[half][k] + p];
            int cnt = 0;
            if (ht < 64) {
#pragma unroll
                for (int q = 0; q < 8; q++) {
                    float acc = 0.f;
#pragma unroll
                    for (int k = 0; k < 16; k++) acc += DKc(q, k) * g[k];
                    bool m = fabsf(acc) > 0.135f;
                    cnt += m ? 1 : 0;
                    GA[half][q * 64 + p] = m ? acc : 0.0f;
                }
            } else {
#pragma unroll
                for (int q = 8; q < 16; q++) {
                    float acc = 0.f;
#pragma unroll
                    for (int k = 0; k < 16; k++) acc += DKc(q, k) * g[k];
                    bool m = fabsf(acc) > 0.135f;
                    cnt += m ? 1 : 0;
                    GA[half][q * 64 + p] = m ? acc : 0.0f;
                }
            }
            cnt = __reduce_add_sync(0xffffffffu, cnt);
            if (lane == 0) atomicAdd(&snnz[half], cnt);
        }
        __syncthreads();
        float wgt = 400.0f / fmaxf((float)snnz[half], 1.0f);

        // --- "inverse" along group axis (DK applied again, ref bug) ---
        if (active) {
            int p = ht & 63;
            float g[16];
#pragma unroll
            for (int k = 0; k < 16; k++) g[k] = GA[half][k * 64 + p];
            if (ht < 64) {
#pragma unroll
                for (int q = 0; q < 8; q++) {
                    float acc = 0.f;
#pragma unroll
                    for (int k = 0; k < 16; k++) acc += DKc(q, k) * g[k];
                    GB[half][q * 64 + p] = acc;
                }
            } else {
#pragma unroll
                for (int q = 8; q < 16; q++) {
                    float acc = 0.f;
#pragma unroll
                    for (int k = 0; k < 16; k++) acc += DKc(q, k) * g[k];
                    GB[half][q * 64 + p] = acc;
                }
            }
        }
        __syncthreads();

        // --- 2D inverse stage 1 ---
        if (active) {
            int p = ht & 63, hh = ht >> 6;
            int a = p >> 3, y = p & 7;
#pragma unroll
            for (int q = 0; q < 8; q++) {
                int k = hh * 8 + q;
                float acc = 0.f;
#pragma unroll
                for (int d = 0; d < 8; d++) acc += GB[half][k * 64 + a * 8 + d] * sD[d * 8 + y];
                GA[half][k * 64 + p] = acc;
            }
        }
        __syncthreads();

        // --- 2D inverse stage 2 + num-only quad scatter + W update ---
        if (active) {
            // 16 patches x 8 rows x 2 quads = 256 items / 128 threads
            for (int item = ht; item < 256; item += 128) {
                int k = item >> 4;
                int rem = item & 15;
                int b = rem >> 1;            // patch row
                int qc = (rem & 1) * 4;      // col quad base (0 or 4)
                float o0 = 0.f, o1 = 0.f, o2 = 0.f, o3 = 0.f;
#pragma unroll
                for (int a = 0; a < 8; a++) {
                    float dv = sD[a * 8 + b];
                    const float* ga = &GA[half][k * 64 + a * 8 + qc];
                    o0 += dv * ga[0];
                    o1 += dv * ga[1];
                    o2 += dv * ga[2];
                    o3 += dv * ga[3];
                }
                int row = selYs[half][k] + b;
                int col = selXs[half][k] + qc;
                float4 v = make_float4(wgt * o0, wgt * o1, wgt * o2, wgt * o3);
                atomicAdd((float4*)(numImg + row * WW + col), v);
            }
            if (ht < KSEL) {
                int ci = selYs[half][ht] >> 2;
                int cj = selXs[half][ht] >> 2;
                atomicAdd(&Wimg[ci * NBLK + cj], wgt);
            }
        }
        __syncthreads();
    }
}

// ---------------------------------------------------------------------------
// Final divide: cnt reconstructed from the per-origin weight map.
// Pixel (y,x) is covered by origins a in {ah-1, ah} per axis (clipped).
// ---------------------------------------------------------------------------
__global__ void div_kernel(float* __restrict__ out) {
    int idx = blockIdx.x * blockDim.x + threadIdx.x;  // NIMG*HH*WW
    int img = idx >> 16;
    int y = (idx >> 8) & 255;
    int x = idx & 255;
    const float* Wimg = g_W + img * (NBLK * NBLK);

    int ayh = min(NBLK - 1, y >> 2);
    int ayl = ayh - 1;
    bool vy = (ayl >= 0) && (ayl * 4 + 7 >= y);
    int axh = min(NBLK - 1, x >> 2);
    int axl = axh - 1;
    bool vx = (axl >= 0) && (axl * 4 + 7 >= x);

    float cnt = Wimg[ayh * NBLK + axh];
    if (vx) cnt += Wimg[ayh * NBLK + axl];
    if (vy) cnt += Wimg[ayl * NBLK + axh];
    if (vy && vx) cnt += Wimg[ayl * NBLK + axl];

    out[idx] = g_num[idx] / fmaxf(cnt, 1e-8f);
}

// ---------------------------------------------------------------------------
extern "C" void kernel_launch(void* const* d_in, const int* in_sizes, int n_in,
                              void* d_out, int out_size) {
    const float* x = (const float*)d_in[0];
    (void)in_sizes; (void)n_in; (void)out_size;

    zero_kernel<<<544, 256>>>();
    dct_kernel<<<(NIMG * NBLK * NBLK + 3) / 4, 256>>>(x);
    nop_kernel<<<1, 32>>>();     // launch-index padding so ncu (-s 5 -c 1)
    nop_kernel<<<1, 32>>>();     // captures bm3d_kernel (launch idx 5)
    nop_kernel<<<1, 32>>>();
    bm3d_kernel<<<dim3(NIMG, 16, NBLK), 256>>>();
    div_kernel<<<2048, 256>>>((float*)d_out);
}

// round 11
// speedup vs baseline: 2.0375x; 1.1276x over previous
#include <cuda_runtime.h>

#define HH 256
#define WW 256
#define NBLK 63
#define CAND 81
#define KSEL 16
#define NIMG 8
#define RP 68   // padded nbT row stride (floats), divisible by 4 (float4 ok)

__device__ __align__(16) float g_T[NIMG * NBLK * NBLK * 64];
__device__ __align__(16) float g_num[NIMG * HH * WW];
__device__ __align__(16) float g_W[NIMG * NBLK * NBLK];

// ---------------------------------------------------------------------------
// Compile-time DCT matrices -> FFMA immediates.
// ---------------------------------------------------------------------------
__device__ __host__ constexpr float COS32(int m) {
    m &= 63;
    if (m > 32) m = 64 - m;
    bool neg = false;
    if (m > 16) { neg = true; m = 32 - m; }
    float v = 0.0f;
    switch (m) {
        case 0:  v = 1.0f; break;
        case 1:  v = 0.99518472667219693f; break;
        case 2:  v = 0.98078528040323044f; break;
        case 3:  v = 0.95694033573220882f; break;
        case 4:  v = 0.92387953251128674f; break;
        case 5:  v = 0.88192126434835505f; break;
        case 6:  v = 0.83146961230254524f; break;
        case 7:  v = 0.77301045336273699f; break;
        case 8:  v = 0.70710678118654752f; break;
        case 9:  v = 0.63439328416364549f; break;
        case 10: v = 0.55557023301960218f; break;
        case 11: v = 0.47139673682599764f; break;
        case 12: v = 0.38268343236508984f; break;
        case 13: v = 0.29028467725446233f; break;
        case 14: v = 0.19509032201612828f; break;
        case 15: v = 0.09801714032956077f; break;
        default: v = 0.0f; break;
    }
    return neg ? -v : v;
}
__device__ __host__ constexpr float DKc(int k, int i) {
    return (k == 0) ? 0.25f : 0.35355339059327373f * COS32((2 * i + 1) * k);
}
__device__ __host__ constexpr float D8c(int k, int i) {
    return (k == 0) ? 0.35355339059327373f : 0.5f * COS32(2 * (2 * i + 1) * k);
}

// ---------------------------------------------------------------------------
__global__ void zero_kernel() {
    int idx = blockIdx.x * blockDim.x + threadIdx.x;
    const int N_NUM4 = NIMG * HH * WW / 4;
    const int N_W4   = NIMG * NBLK * NBLK / 4;
    if (idx < N_NUM4)
        ((float4*)g_num)[idx] = make_float4(0.f, 0.f, 0.f, 0.f);
    else if (idx < N_NUM4 + N_W4)
        ((float4*)g_W)[idx - N_NUM4] = make_float4(0.f, 0.f, 0.f, 0.f);
}

__global__ void nop_kernel() {}

// ---------------------------------------------------------------------------
// 8x8 DCT of every patch
// ---------------------------------------------------------------------------
__global__ void dct_kernel(const float* __restrict__ x) {
    __shared__ float sD[64];
    __shared__ float sp[4][64];
    __shared__ float st[4][64];
    int t = threadIdx.x;
    if (t < 64) {
        int k = t >> 3, i = t & 7;
        sD[t] = D8c(k, i);
    }
    int grp = t >> 6;
    int lt = t & 63;
    int pid = blockIdx.x * 4 + grp;
    bool valid = pid < NIMG * NBLK * NBLK;
    int img = 0, bi = 0, bj = 0;
    if (valid) {
        img = pid / (NBLK * NBLK);
        int r = pid % (NBLK * NBLK);
        bi = r / NBLK; bj = r % NBLK;
    }
    __syncthreads();
    if (valid) {
        int b = lt >> 3, c = lt & 7;
        float v = x[img * (HH * WW) + (bi * 4 + b) * WW + (bj * 4 + c)];
        sp[grp][lt] = fminf(fmaxf(v, 0.0f), 1.0f);
    }
    __syncthreads();
    if (valid) {
        int a = lt >> 3, c = lt & 7;
        float acc = 0.f;
#pragma unroll
        for (int b = 0; b < 8; b++) acc += sD[a * 8 + b] * sp[grp][b * 8 + c];
        st[grp][lt] = acc;
    }
    __syncthreads();
    if (valid) {
        int a = lt >> 3, d = lt & 7;
        float acc = 0.f;
#pragma unroll
        for (int c = 0; c < 8; c++) acc += st[grp][a * 8 + c] * sD[d * 8 + c];
        g_T[pid * 64 + lt] = acc;
    }
}

// ---------------------------------------------------------------------------
// Main pipeline: 256 threads = two independent 128-thread halves.
// ---------------------------------------------------------------------------
__global__ void __launch_bounds__(256) bm3d_kernel() {
    __shared__ float nbT[9 * 12 * RP];
    __shared__ float GA[2][16 * 64];
    __shared__ float GB[2][16 * 64];
    __shared__ float sD[64];
    __shared__ float sdist[2][CAND];
    __shared__ int selOff[2][KSEL];
    __shared__ int selYs[2][KSEL];
    __shared__ int selXs[2][KSEL];
    __shared__ int snnz[2];

    int t = threadIdx.x;
    int img = blockIdx.x;
    int j0 = blockIdx.y * 4;
    int i = blockIdx.z;
    int nb = min(4, NBLK - j0);

    int half = t >> 7;
    int ht   = t & 127;
    int lane = t & 31;
    int hwarp = ht >> 5;
    int grpL = lane >> 3;
    int sub  = lane & 7;

    if (t < 64) {
        int k = t >> 3, ii = t & 7;
        sD[t] = D8c(k, ii);
    }

    // --- tile fill with float4 (1728 LDG.128 per CTA) ---
    const float* Timg = g_T + img * (NBLK * NBLK * 64);
    for (int idx4 = t; idx4 < 9 * 12 * 16; idx4 += 256) {
        int rs = idx4 >> 4;                  // row-pair index 0..107
        int p4 = (idx4 & 15) * 4;            // float offset within 64
        int r = rs / 12;
        int s = rs % 12;
        int ci = min(max(i - 4 + r, 0), NBLK - 1);
        int cj = min(max(j0 - 4 + s, 0), NBLK - 1);
        float4 v = *(const float4*)(Timg + (ci * NBLK + cj) * 64 + p4);
        *(float4*)(&nbT[rs * RP + p4]) = v;
    }
    __syncthreads();

    float* numImg = g_num + img * (HH * WW);
    float* Wimg   = g_W + img * (NBLK * NBLK);

    for (int jp = 0; jp < 2; jp++) {
        int jb = jp * 2 + half;
        bool active = jb < nb;
        int j = j0 + jb;
        if (ht == 0) snnz[half] = 0;

        // --- candidate distances: ref patch hoisted to registers, float4 LDS ---
        if (active) {
            const float* rp = &nbT[(4 * 12 + jb + 4) * RP + sub * 8];
            float4 rv0 = *(const float4*)(rp);
            float4 rv1 = *(const float4*)(rp + 4);
            for (int cb = hwarp * 4; cb < CAND; cb += 16) {
                int cid = min(cb + grpL, CAND - 1);
                int rr = cid / 9;
                int sc = jb + (cid % 9);
                const float* cp = &nbT[(rr * 12 + sc) * RP + sub * 8];
                float4 cv0 = *(const float4*)(cp);
                float4 cv1 = *(const float4*)(cp + 4);
                float d0 = cv0.x - rv0.x, d1 = cv0.y - rv0.y;
                float acc = d0 * d0 + d1 * d1;
                d0 = cv0.z - rv0.z; d1 = cv0.w - rv0.w;
                acc += d0 * d0 + d1 * d1;
                d0 = cv1.x - rv1.x; d1 = cv1.y - rv1.y;
                acc += d0 * d0 + d1 * d1;
                d0 = cv1.z - rv1.z; d1 = cv1.w - rv1.w;
                acc += d0 * d0 + d1 * d1;
                acc += __shfl_xor_sync(0xffffffffu, acc, 1);
                acc += __shfl_xor_sync(0xffffffffu, acc, 2);
                acc += __shfl_xor_sync(0xffffffffu, acc, 4);
                if (sub == 0 && cb + grpL < CAND) sdist[half][cid] = acc;
            }
        }
        __syncthreads();

        // --- rank-based top-16, ties -> lower candidate index ---
        if (active && ht < CAND) {
            const float* ds = sdist[half];
            float my = ds[ht];
            int rank = 0;
            for (int c = 0; c < CAND; c++) {
                float dc = ds[c];
                rank += (dc < my) || (dc == my && c < ht);
            }
            if (rank < KSEL) {
                int rr = ht / 9;
                int dx = ht % 9;
                selOff[half][rank] = (rr * 12 + jb + dx) * RP;
                int ci = min(max(i - 4 + rr, 0), NBLK - 1);
                int cj = min(max(j - 4 + dx, 0), NBLK - 1);
                selYs[half][rank] = ci * 4;
                selXs[half][rank] = cj * 4;
            }
        }
        __syncthreads();

        // --- forward DCT16 (immediates) + threshold + nnz ---
        if (active) {
            int p = ht & 63;
            float g[16];
#pragma unroll
            for (int k = 0; k < 16; k++) g[k] = nbT[selOff[half][k] + p];
            int cnt = 0;
            if (ht < 64) {
#pragma unroll
                for (int q = 0; q < 8; q++) {
                    float acc = 0.f;
#pragma unroll
                    for (int k = 0; k < 16; k++) acc += DKc(q, k) * g[k];
                    bool m = fabsf(acc) > 0.135f;
                    cnt += m ? 1 : 0;
                    GA[half][q * 64 + p] = m ? acc : 0.0f;
                }
            } else {
#pragma unroll
                for (int q = 8; q < 16; q++) {
                    float acc = 0.f;
#pragma unroll
                    for (int k = 0; k < 16; k++) acc += DKc(q, k) * g[k];
                    bool m = fabsf(acc) > 0.135f;
                    cnt += m ? 1 : 0;
                    GA[half][q * 64 + p] = m ? acc : 0.0f;
                }
            }
            cnt = __reduce_add_sync(0xffffffffu, cnt);
            if (lane == 0) atomicAdd(&snnz[half], cnt);
        }
        __syncthreads();
        float wgt = 400.0f / fmaxf((float)snnz[half], 1.0f);

        // --- "inverse" along group axis (DK applied again, ref bug) ---
        if (active) {
            int p = ht & 63;
            float g[16];
#pragma unroll
            for (int k = 0; k < 16; k++) g[k] = GA[half][k * 64 + p];
            if (ht < 64) {
#pragma unroll
                for (int q = 0; q < 8; q++) {
                    float acc = 0.f;
#pragma unroll
                    for (int k = 0; k < 16; k++) acc += DKc(q, k) * g[k];
                    GB[half][q * 64 + p] = acc;
                }
            } else {
#pragma unroll
                for (int q = 8; q < 16; q++) {
                    float acc = 0.f;
#pragma unroll
                    for (int k = 0; k < 16; k++) acc += DKc(q, k) * g[k];
                    GB[half][q * 64 + p] = acc;
                }
            }
        }
        __syncthreads();

        // --- 2D inverse stage 1 (float4 reads along d) ---
        if (active) {
            int p = ht & 63, hh = ht >> 6;
            int a = p >> 3, y = p & 7;
#pragma unroll
            for (int q = 0; q < 8; q++) {
                int k = hh * 8 + q;
                const float* gb = &GB[half][k * 64 + a * 8];
                float4 b0 = *(const float4*)(gb);
                float4 b1 = *(const float4*)(gb + 4);
                float acc = b0.x * sD[0 * 8 + y] + b0.y * sD[1 * 8 + y] +
                            b0.z * sD[2 * 8 + y] + b0.w * sD[3 * 8 + y] +
                            b1.x * sD[4 * 8 + y] + b1.y * sD[5 * 8 + y] +
                            b1.z * sD[6 * 8 + y] + b1.w * sD[7 * 8 + y];
                GA[half][k * 64 + p] = acc;
            }
        }
        __syncthreads();

        // --- 2D inverse stage 2 + num-only quad scatter + W update ---
        if (active) {
            for (int item = ht; item < 256; item += 128) {
                int k = item >> 4;
                int rem = item & 15;
                int b = rem >> 1;
                int qc = (rem & 1) * 4;
                float o0 = 0.f, o1 = 0.f, o2 = 0.f, o3 = 0.f;
#pragma unroll
                for (int a = 0; a < 8; a++) {
                    float dv = sD[a * 8 + b];
                    float4 ga = *(const float4*)(&GA[half][k * 64 + a * 8 + qc]);
                    o0 += dv * ga.x;
                    o1 += dv * ga.y;
                    o2 += dv * ga.z;
                    o3 += dv * ga.w;
                }
                int row = selYs[half][k] + b;
                int col = selXs[half][k] + qc;
                float4 v = make_float4(wgt * o0, wgt * o1, wgt * o2, wgt * o3);
                atomicAdd((float4*)(numImg + row * WW + col), v);
            }
            if (ht < KSEL) {
                int ci = selYs[half][ht] >> 2;
                int cj = selXs[half][ht] >> 2;
                atomicAdd(&Wimg[ci * NBLK + cj], wgt);
            }
        }
        __syncthreads();
    }
}

// ---------------------------------------------------------------------------
// Final divide: cnt reconstructed from the per-origin weight map.
// ---------------------------------------------------------------------------
__global__ void div_kernel(float* __restrict__ out) {
    int idx = blockIdx.x * blockDim.x + threadIdx.x;
    int img = idx >> 16;
    int y = (idx >> 8) & 255;
    int x = idx & 255;
    const float* Wimg = g_W + img * (NBLK * NBLK);

    int ayh = min(NBLK - 1, y >> 2);
    int ayl = ayh - 1;
    bool vy = (ayl >= 0) && (ayl * 4 + 7 >= y);
    int axh = min(NBLK - 1, x >> 2);
    int axl = axh - 1;
    bool vx = (axl >= 0) && (axl * 4 + 7 >= x);

    float cnt = Wimg[ayh * NBLK + axh];
    if (vx) cnt += Wimg[ayh * NBLK + axl];
    if (vy) cnt += Wimg[ayl * NBLK + axh];
    if (vy && vx) cnt += Wimg[ayl * NBLK + axl];

    out[idx] = g_num[idx] / fmaxf(cnt, 1e-8f);
}

// ---------------------------------------------------------------------------
extern "C" void kernel_launch(void* const* d_in, const int* in_sizes, int n_in,
                              void* d_out, int out_size) {
    const float* x = (const float*)d_in[0];
    (void)in_sizes; (void)n_in; (void)out_size;

    zero_kernel<<<544, 256>>>();                                 // idx 0
    dct_kernel<<<(NIMG * NBLK * NBLK + 3) / 4, 256>>>(x);        // idx 1
    nop_kernel<<<1, 32>>>();                                     // idx 2
    bm3d_kernel<<<dim3(NIMG, 16, NBLK), 256>>>();                // idx 3 <- ncu capture slot
    div_kernel<<<2048, 256>>>((float*)d_out);                    // idx 4
}

// round 12
// speedup vs baseline: 2.4174x; 1.1865x over previous
#include <cuda_runtime.h>

#define HH 256
#define WW 256
#define NBLK 63
#define CAND 81
#define KSEL 16
#define NIMG 8
#define RP 64   // nbT row stride: float4 patterns make padding useless (see R11 analysis)

__device__ __align__(16) float g_T[NIMG * NBLK * NBLK * 64];
__device__ __align__(16) float g_num[NIMG * HH * WW];
__device__ __align__(16) float g_W[NIMG * NBLK * NBLK];

// ---------------------------------------------------------------------------
// Compile-time DCT matrices -> FFMA immediates.
// ---------------------------------------------------------------------------
__device__ __host__ constexpr float COS32(int m) {
    m &= 63;
    if (m > 32) m = 64 - m;
    bool neg = false;
    if (m > 16) { neg = true; m = 32 - m; }
    float v = 0.0f;
    switch (m) {
        case 0:  v = 1.0f; break;
        case 1:  v = 0.99518472667219693f; break;
        case 2:  v = 0.98078528040323044f; break;
        case 3:  v = 0.95694033573220882f; break;
        case 4:  v = 0.92387953251128674f; break;
        case 5:  v = 0.88192126434835505f; break;
        case 6:  v = 0.83146961230254524f; break;
        case 7:  v = 0.77301045336273699f; break;
        case 8:  v = 0.70710678118654752f; break;
        case 9:  v = 0.63439328416364549f; break;
        case 10: v = 0.55557023301960218f; break;
        case 11: v = 0.47139673682599764f; break;
        case 12: v = 0.38268343236508984f; break;
        case 13: v = 0.29028467725446233f; break;
        case 14: v = 0.19509032201612828f; break;
        case 15: v = 0.09801714032956077f; break;
        default: v = 0.0f; break;
    }
    return neg ? -v : v;
}
__device__ __host__ constexpr float DKc(int k, int i) {
    return (k == 0) ? 0.25f : 0.35355339059327373f * COS32((2 * i + 1) * k);
}
__device__ __host__ constexpr float D8c(int k, int i) {
    return (k == 0) ? 0.35355339059327373f : 0.5f * COS32(2 * (2 * i + 1) * k);
}

// ---------------------------------------------------------------------------
__global__ void zero_kernel() {
    int idx = blockIdx.x * blockDim.x + threadIdx.x;
    const int N_NUM4 = NIMG * HH * WW / 4;
    const int N_W4   = NIMG * NBLK * NBLK / 4;
    if (idx < N_NUM4)
        ((float4*)g_num)[idx] = make_float4(0.f, 0.f, 0.f, 0.f);
    else if (idx < N_NUM4 + N_W4)
        ((float4*)g_W)[idx - N_NUM4] = make_float4(0.f, 0.f, 0.f, 0.f);
}

__global__ void nop_kernel() {}

// ---------------------------------------------------------------------------
// 8x8 DCT of every patch
// ---------------------------------------------------------------------------
__global__ void dct_kernel(const float* __restrict__ x) {
    __shared__ float sD[64];
    __shared__ float sp[4][64];
    __shared__ float st[4][64];
    int t = threadIdx.x;
    if (t < 64) {
        int k = t >> 3, i = t & 7;
        sD[t] = D8c(k, i);
    }
    int grp = t >> 6;
    int lt = t & 63;
    int pid = blockIdx.x * 4 + grp;
    bool valid = pid < NIMG * NBLK * NBLK;
    int img = 0, bi = 0, bj = 0;
    if (valid) {
        img = pid / (NBLK * NBLK);
        int r = pid % (NBLK * NBLK);
        bi = r / NBLK; bj = r % NBLK;
    }
    __syncthreads();
    if (valid) {
        int b = lt >> 3, c = lt & 7;
        float v = x[img * (HH * WW) + (bi * 4 + b) * WW + (bj * 4 + c)];
        sp[grp][lt] = fminf(fmaxf(v, 0.0f), 1.0f);
    }
    __syncthreads();
    if (valid) {
        int a = lt >> 3, c = lt & 7;
        float acc = 0.f;
#pragma unroll
        for (int b = 0; b < 8; b++) acc += sD[a * 8 + b] * sp[grp][b * 8 + c];
        st[grp][lt] = acc;
    }
    __syncthreads();
    if (valid) {
        int a = lt >> 3, d = lt & 7;
        float acc = 0.f;
#pragma unroll
        for (int c = 0; c < 8; c++) acc += st[grp][a * 8 + c] * sD[d * 8 + c];
        g_T[pid * 64 + lt] = acc;
    }
}

// ---------------------------------------------------------------------------
// Main pipeline: 256 threads = two 128-thread halves; 5 CTAs/SM target.
// sdist aliases GA (disjoint live ranges, barrier-separated).
// smem = 27648 + 8192 + 8192 + 256 + 384 + 8 = 44680 B.
// ---------------------------------------------------------------------------
__global__ void __launch_bounds__(256, 5) bm3d_kernel() {
    __shared__ float nbT[9 * 12 * RP];          // 27648 B
    __shared__ float GA[2][16 * 64];            // 8192 B (front 82 floats double as sdist)
    __shared__ float GB[2][16 * 64];            // 8192 B
    __shared__ float sD[64];
    __shared__ int selOff[2][KSEL];
    __shared__ int selYs[2][KSEL];
    __shared__ int selXs[2][KSEL];
    __shared__ int snnz[2];

    int t = threadIdx.x;
    int img = blockIdx.x;
    int j0 = blockIdx.y * 4;
    int i = blockIdx.z;
    int nb = min(4, NBLK - j0);

    int half = t >> 7;
    int ht   = t & 127;
    int lane = t & 31;
    int hwarp = ht >> 5;
    int grpL = lane >> 3;
    int sub  = lane & 7;

    if (t < 64) {
        int k = t >> 3, ii = t & 7;
        sD[t] = D8c(k, ii);
    }

    // --- tile fill: RP=64 makes nbT a linear copy of clipped patch rows ---
    const float* Timg = g_T + img * (NBLK * NBLK * 64);
    for (int idx4 = t; idx4 < 9 * 12 * 16; idx4 += 256) {
        int rs = idx4 >> 4;
        int p4 = (idx4 & 15) * 4;
        int r = rs / 12;
        int s = rs % 12;
        int ci = min(max(i - 4 + r, 0), NBLK - 1);
        int cj = min(max(j0 - 4 + s, 0), NBLK - 1);
        float4 v = *(const float4*)(Timg + (ci * NBLK + cj) * 64 + p4);
        *(float4*)(&nbT[rs * RP + p4]) = v;
    }
    __syncthreads();

    float* numImg = g_num + img * (HH * WW);
    float* Wimg   = g_W + img * (NBLK * NBLK);

    for (int jp = 0; jp < 2; jp++) {
        int jb = jp * 2 + half;
        bool active = jb < nb;
        int j = j0 + jb;
        float* sdist_h = &GA[half][0];          // alias: dead GA space
        if (ht == 0) {
            snnz[half] = 0;
            sdist_h[CAND] = 3.4e38f;            // +inf pad for float2 rank scan
        }

        // --- candidate distances: ref patch hoisted, float4 LDS ---
        if (active) {
            const float* rp = &nbT[((4 * 12 + jb + 4) << 6) + sub * 8];
            float4 rv0 = *(const float4*)(rp);
            float4 rv1 = *(const float4*)(rp + 4);
            for (int cb = hwarp * 4; cb < CAND; cb += 16) {
                int cid = min(cb + grpL, CAND - 1);
                int rr = cid / 9;
                int sc = jb + (cid % 9);
                const float* cp = &nbT[((rr * 12 + sc) << 6) + sub * 8];
                float4 cv0 = *(const float4*)(cp);
                float4 cv1 = *(const float4*)(cp + 4);
                float d0 = cv0.x - rv0.x, d1 = cv0.y - rv0.y;
                float acc = d0 * d0 + d1 * d1;
                d0 = cv0.z - rv0.z; d1 = cv0.w - rv0.w;
                acc += d0 * d0 + d1 * d1;
                d0 = cv1.x - rv1.x; d1 = cv1.y - rv1.y;
                acc += d0 * d0 + d1 * d1;
                d0 = cv1.z - rv1.z; d1 = cv1.w - rv1.w;
                acc += d0 * d0 + d1 * d1;
                acc += __shfl_xor_sync(0xffffffffu, acc, 1);
                acc += __shfl_xor_sync(0xffffffffu, acc, 2);
                acc += __shfl_xor_sync(0xffffffffu, acc, 4);
                if (sub == 0 && cb + grpL < CAND) sdist_h[cid] = acc;
            }
        }
        __syncthreads();

        // --- rank-based top-16 (float2 scan), ties -> lower index ---
        if (active && ht < CAND) {
            const float2* ds2 = (const float2*)sdist_h;
            float my = sdist_h[ht];
            int rank = 0;
#pragma unroll
            for (int c2 = 0; c2 < (CAND + 1) / 2; c2++) {
                float2 dp = ds2[c2];
                rank += (dp.x < my) || (dp.x == my && (2 * c2) < ht);
                rank += (dp.y < my) || (dp.y == my && (2 * c2 + 1) < ht);
            }
            if (rank < KSEL) {
                int rr = ht / 9;
                int dx = ht % 9;
                selOff[half][rank] = (rr * 12 + jb + dx) << 6;
                int ci = min(max(i - 4 + rr, 0), NBLK - 1);
                int cj = min(max(j - 4 + dx, 0), NBLK - 1);
                selYs[half][rank] = ci * 4;
                selXs[half][rank] = cj * 4;
            }
        }
        __syncthreads();

        // --- forward DCT16 (immediates) + threshold + nnz ---
        if (active) {
            int p = ht & 63;
            float g[16];
#pragma unroll
            for (int k = 0; k < 16; k++) g[k] = nbT[selOff[half][k] + p];
            int cnt = 0;
            if (ht < 64) {
#pragma unroll
                for (int q = 0; q < 8; q++) {
                    float acc = 0.f;
#pragma unroll
                    for (int k = 0; k < 16; k++) acc += DKc(q, k) * g[k];
                    bool m = fabsf(acc) > 0.135f;
                    cnt += m ? 1 : 0;
                    GA[half][q * 64 + p] = m ? acc : 0.0f;
                }
            } else {
#pragma unroll
                for (int q = 8; q < 16; q++) {
                    float acc = 0.f;
#pragma unroll
                    for (int k = 0; k < 16; k++) acc += DKc(q, k) * g[k];
                    bool m = fabsf(acc) > 0.135f;
                    cnt += m ? 1 : 0;
                    GA[half][q * 64 + p] = m ? acc : 0.0f;
                }
            }
            cnt = __reduce_add_sync(0xffffffffu, cnt);
            if (lane == 0) atomicAdd(&snnz[half], cnt);
        }
        __syncthreads();
        float wgt = 400.0f / fmaxf((float)snnz[half], 1.0f);

        // --- "inverse" along group axis (DK applied again, ref bug) ---
        if (active) {
            int p = ht & 63;
            float g[16];
#pragma unroll
            for (int k = 0; k < 16; k++) g[k] = GA[half][k * 64 + p];
            if (ht < 64) {
#pragma unroll
                for (int q = 0; q < 8; q++) {
                    float acc = 0.f;
#pragma unroll
                    for (int k = 0; k < 16; k++) acc += DKc(q, k) * g[k];
                    GB[half][q * 64 + p] = acc;
                }
            } else {
#pragma unroll
                for (int q = 8; q < 16; q++) {
                    float acc = 0.f;
#pragma unroll
                    for (int k = 0; k < 16; k++) acc += DKc(q, k) * g[k];
                    GB[half][q * 64 + p] = acc;
                }
            }
        }
        __syncthreads();

        // --- 2D inverse stage 1 (float4 reads along d) ---
        if (active) {
            int p = ht & 63, hh = ht >> 6;
            int a = p >> 3, y = p & 7;
#pragma unroll
            for (int q = 0; q < 8; q++) {
                int k = hh * 8 + q;
                const float* gb = &GB[half][k * 64 + a * 8];
                float4 b0 = *(const float4*)(gb);
                float4 b1 = *(const float4*)(gb + 4);
                float acc = b0.x * sD[0 * 8 + y] + b0.y * sD[1 * 8 + y] +
                            b0.z * sD[2 * 8 + y] + b0.w * sD[3 * 8 + y] +
                            b1.x * sD[4 * 8 + y] + b1.y * sD[5 * 8 + y] +
                            b1.z * sD[6 * 8 + y] + b1.w * sD[7 * 8 + y];
                GA[half][k * 64 + p] = acc;
            }
        }
        __syncthreads();

        // --- 2D inverse stage 2 + num-only quad scatter + W update ---
        if (active) {
            for (int item = ht; item < 256; item += 128) {
                int k = item >> 4;
                int rem = item & 15;
                int b = rem >> 1;
                int qc = (rem & 1) * 4;
                float o0 = 0.f, o1 = 0.f, o2 = 0.f, o3 = 0.f;
#pragma unroll
                for (int a = 0; a < 8; a++) {
                    float dv = sD[a * 8 + b];
                    float4 ga = *(const float4*)(&GA[half][k * 64 + a * 8 + qc]);
                    o0 += dv * ga.x;
                    o1 += dv * ga.y;
                    o2 += dv * ga.z;
                    o3 += dv * ga.w;
                }
                int row = selYs[half][k] + b;
                int col = selXs[half][k] + qc;
                float4 v = make_float4(wgt * o0, wgt * o1, wgt * o2, wgt * o3);
                atomicAdd((float4*)(numImg + row * WW + col), v);
            }
            if (ht < KSEL) {
                int ci = selYs[half][ht] >> 2;
                int cj = selXs[half][ht] >> 2;
                atomicAdd(&Wimg[ci * NBLK + cj], wgt);
            }
        }
        __syncthreads();
    }
}

// ---------------------------------------------------------------------------
// Final divide: cnt reconstructed from the per-origin weight map.
// ---------------------------------------------------------------------------
__global__ void div_kernel(float* __restrict__ out) {
    int idx = blockIdx.x * blockDim.x + threadIdx.x;
    int img = idx >> 16;
    int y = (idx >> 8) & 255;
    int x = idx & 255;
    const float* Wimg = g_W + img * (NBLK * NBLK);

    int ayh = min(NBLK - 1, y >> 2);
    int ayl = ayh - 1;
    bool vy = (ayl >= 0) && (ayl * 4 + 7 >= y);
    int axh = min(NBLK - 1, x >> 2);
    int axl = axh - 1;
    bool vx = (axl >= 0) && (axl * 4 + 7 >= x);

    float cnt = Wimg[ayh * NBLK + axh];
    if (vx) cnt += Wimg[ayh * NBLK + axl];
    if (vy) cnt += Wimg[ayl * NBLK + axh];
    if (vy && vx) cnt += Wimg[ayl * NBLK + axl];

    out[idx] = g_num[idx] / fmaxf(cnt, 1e-8f);
}

// ---------------------------------------------------------------------------
extern "C" void kernel_launch(void* const* d_in, const int* in_sizes, int n_in,
                              void* d_out, int out_size) {
    const float* x = (const float*)d_in[0];
    (void)in_sizes; (void)n_in; (void)out_size;

    zero_kernel<<<544, 256>>>();                                 // idx 0
    dct_kernel<<<(NIMG * NBLK * NBLK + 3) / 4, 256>>>(x);        // idx 1
    nop_kernel<<<1, 32>>>();                                     // idx 2
    bm3d_kernel<<<dim3(NIMG, 16, NBLK), 256>>>();                // idx 3 <- ncu capture slot
    div_kernel<<<2048, 256>>>((float*)d_out);                    // idx 4
}

// round 13
// speedup vs baseline: 2.5156x; 1.0406x over previous
#include <cuda_runtime.h>

#define HH 256
#define WW 256
#define NBLK 63
#define CAND 81
#define KSEL 16
#define NIMG 8
#define NW 10   // window cols per CTA (2 jb: dx 0..8 + jb 0..1)

__device__ __align__(16) float g_T[NIMG * NBLK * NBLK * 64];
__device__ __align__(16) float g_num[NIMG * HH * WW];
__device__ __align__(16) float g_W[NIMG * NBLK * NBLK];

// ---------------------------------------------------------------------------
// Compile-time DCT matrices -> FFMA immediates.
// ---------------------------------------------------------------------------
__device__ __host__ constexpr float COS32(int m) {
    m &= 63;
    if (m > 32) m = 64 - m;
    bool neg = false;
    if (m > 16) { neg = true; m = 32 - m; }
    float v = 0.0f;
    switch (m) {
        case 0:  v = 1.0f; break;
        case 1:  v = 0.99518472667219693f; break;
        case 2:  v = 0.98078528040323044f; break;
        case 3:  v = 0.95694033573220882f; break;
        case 4:  v = 0.92387953251128674f; break;
        case 5:  v = 0.88192126434835505f; break;
        case 6:  v = 0.83146961230254524f; break;
        case 7:  v = 0.77301045336273699f; break;
        case 8:  v = 0.70710678118654752f; break;
        case 9:  v = 0.63439328416364549f; break;
        case 10: v = 0.55557023301960218f; break;
        case 11: v = 0.47139673682599764f; break;
        case 12: v = 0.38268343236508984f; break;
        case 13: v = 0.29028467725446233f; break;
        case 14: v = 0.19509032201612828f; break;
        case 15: v = 0.09801714032956077f; break;
        default: v = 0.0f; break;
    }
    return neg ? -v : v;
}
__device__ __host__ constexpr float DKc(int k, int i) {
    return (k == 0) ? 0.25f : 0.35355339059327373f * COS32((2 * i + 1) * k);
}
__device__ __host__ constexpr float D8c(int k, int i) {
    return (k == 0) ? 0.35355339059327373f : 0.5f * COS32(2 * (2 * i + 1) * k);
}

// ---------------------------------------------------------------------------
__global__ void zero_kernel() {
    int idx = blockIdx.x * blockDim.x + threadIdx.x;
    const int N_NUM4 = NIMG * HH * WW / 4;
    const int N_W4   = NIMG * NBLK * NBLK / 4;
    if (idx < N_NUM4)
        ((float4*)g_num)[idx] = make_float4(0.f, 0.f, 0.f, 0.f);
    else if (idx < N_NUM4 + N_W4)
        ((float4*)g_W)[idx - N_NUM4] = make_float4(0.f, 0.f, 0.f, 0.f);
}

__global__ void nop_kernel() {}

// ---------------------------------------------------------------------------
// 8x8 DCT of every patch
// ---------------------------------------------------------------------------
__global__ void dct_kernel(const float* __restrict__ x) {
    __shared__ float sD[64];
    __shared__ float sp[4][64];
    __shared__ float st[4][64];
    int t = threadIdx.x;
    if (t < 64) {
        int k = t >> 3, i = t & 7;
        sD[t] = D8c(k, i);
    }
    int grp = t >> 6;
    int lt = t & 63;
    int pid = blockIdx.x * 4 + grp;
    bool valid = pid < NIMG * NBLK * NBLK;
    int img = 0, bi = 0, bj = 0;
    if (valid) {
        img = pid / (NBLK * NBLK);
        int r = pid % (NBLK * NBLK);
        bi = r / NBLK; bj = r % NBLK;
    }
    __syncthreads();
    if (valid) {
        int b = lt >> 3, c = lt & 7;
        float v = x[img * (HH * WW) + (bi * 4 + b) * WW + (bj * 4 + c)];
        sp[grp][lt] = fminf(fmaxf(v, 0.0f), 1.0f);
    }
    __syncthreads();
    if (valid) {
        int a = lt >> 3, c = lt & 7;
        float acc = 0.f;
#pragma unroll
        for (int b = 0; b < 8; b++) acc += sD[a * 8 + b] * sp[grp][b * 8 + c];
        st[grp][lt] = acc;
    }
    __syncthreads();
    if (valid) {
        int a = lt >> 3, d = lt & 7;
        float acc = 0.f;
#pragma unroll
        for (int c = 0; c < 8; c++) acc += st[grp][a * 8 + c] * sD[d * 8 + c];
        g_T[pid * 64 + lt] = acc;
    }
}

// ---------------------------------------------------------------------------
// Main pipeline: 256 threads = two 128-thread halves, ONE jb per half.
// nbT dead after gather -> GA/GB alias its front. smem ~25KB, 6 CTAs/SM.
// ---------------------------------------------------------------------------
__global__ void __launch_bounds__(256, 6) bm3d_kernel() {
    __shared__ float nbT[9 * NW * 64];              // 23040 B; front 16KB reused as GA/GB
    __shared__ float sD[64];
    __shared__ __align__(16) float sdist[2][84];    // [81]=+inf pad
    __shared__ int selOff[2][KSEL];
    __shared__ int selYs[2][KSEL];
    __shared__ int selXs[2][KSEL];
    __shared__ int snnz[2];

    int t = threadIdx.x;
    int img = blockIdx.x;
    int j0 = blockIdx.y * 2;
    int i = blockIdx.z;

    int half = t >> 7;
    int ht   = t & 127;
    int lane = t & 31;
    int hwarp = ht >> 5;
    int grpL = lane >> 3;
    int sub  = lane & 7;
    int p    = ht & 63;

    int j = j0 + half;              // this half's reference block column
    bool active = j < NBLK;

    float* GA_h = nbT + half * 1024;            // alias (nbT dead after gather)
    float* GB_h = nbT + 2048 + half * 1024;

    if (t < 64) {
        int k = t >> 3, ii = t & 7;
        sD[t] = D8c(k, ii);
    }
    if (ht == 0) {
        snnz[half] = 0;
        sdist[half][81] = 3.4e38f;
    }

    // --- tile fill (9 x NW patch window) ---
    const float* Timg = g_T + img * (NBLK * NBLK * 64);
    for (int idx4 = t; idx4 < 9 * NW * 16; idx4 += 256) {
        int rs = idx4 >> 4;
        int p4 = (idx4 & 15) * 4;
        int r = rs / NW;
        int s = rs % NW;
        int ci = min(max(i - 4 + r, 0), NBLK - 1);
        int cj = min(max(j0 - 4 + s, 0), NBLK - 1);
        float4 v = *(const float4*)(Timg + (ci * NBLK + cj) * 64 + p4);
        *(float4*)(&nbT[(rs << 6) + p4]) = v;
    }
    __syncthreads();

    float* numImg = g_num + img * (HH * WW);
    float* Wimg   = g_W + img * (NBLK * NBLK);

    // --- candidate distances: ref patch hoisted, float4 LDS ---
    if (active) {
        const float* rp = &nbT[((4 * NW + half + 4) << 6) + sub * 8];
        float4 rv0 = *(const float4*)(rp);
        float4 rv1 = *(const float4*)(rp + 4);
        for (int cb = hwarp * 4; cb < CAND; cb += 16) {
            int cid = min(cb + grpL, CAND - 1);
            int rr = cid / 9;
            int sc = half + (cid % 9);
            const float* cp = &nbT[((rr * NW + sc) << 6) + sub * 8];
            float4 cv0 = *(const float4*)(cp);
            float4 cv1 = *(const float4*)(cp + 4);
            float d0 = cv0.x - rv0.x, d1 = cv0.y - rv0.y;
            float acc = d0 * d0 + d1 * d1;
            d0 = cv0.z - rv0.z; d1 = cv0.w - rv0.w;
            acc += d0 * d0 + d1 * d1;
            d0 = cv1.x - rv1.x; d1 = cv1.y - rv1.y;
            acc += d0 * d0 + d1 * d1;
            d0 = cv1.z - rv1.z; d1 = cv1.w - rv1.w;
            acc += d0 * d0 + d1 * d1;
            acc += __shfl_xor_sync(0xffffffffu, acc, 1);
            acc += __shfl_xor_sync(0xffffffffu, acc, 2);
            acc += __shfl_xor_sync(0xffffffffu, acc, 4);
            if (sub == 0 && cb + grpL < CAND) sdist[half][cid] = acc;
        }
    }
    __syncthreads();

    // --- rank-based top-16 (float2 scan), ties -> lower index ---
    if (active && ht < CAND) {
        const float2* ds2 = (const float2*)&sdist[half][0];
        float my = sdist[half][ht];
        int rank = 0;
#pragma unroll
        for (int c2 = 0; c2 < (CAND + 1) / 2; c2++) {
            float2 dp = ds2[c2];
            rank += (dp.x < my) || (dp.x == my && (2 * c2) < ht);
            rank += (dp.y < my) || (dp.y == my && (2 * c2 + 1) < ht);
        }
        if (rank < KSEL) {
            int rr = ht / 9;
            int dx = ht % 9;
            selOff[half][rank] = (rr * NW + half + dx) << 6;
            int ci = min(max(i - 4 + rr, 0), NBLK - 1);
            int cj = min(max(j - 4 + dx, 0), NBLK - 1);
            selYs[half][rank] = ci * 4;
            selXs[half][rank] = cj * 4;
        }
    }
    __syncthreads();

    // --- gather group into regs; form even/odd sums (DCT16 symmetry) ---
    float s8[8], d8[8];
    if (active) {
        float g[16];
#pragma unroll
        for (int k = 0; k < 16; k++) g[k] = nbT[selOff[half][k] + p];
#pragma unroll
        for (int k = 0; k < 8; k++) {
            s8[k] = g[k] + g[15 - k];
            d8[k] = g[k] - g[15 - k];
        }
    }
    __syncthreads();   // all nbT reads done -> GA/GB alias region writable

    // --- forward DCT16 (immediates, even/odd) + threshold + nnz -> GA ---
    if (active) {
        int cnt = 0;
        if (ht < 64) {
#pragma unroll
            for (int q = 0; q < 8; q++) {
                float acc = 0.f;
#pragma unroll
                for (int k = 0; k < 8; k++)
                    acc += DKc(q, k) * ((q & 1) ? d8[k] : s8[k]);
                bool m = fabsf(acc) > 0.135f;
                cnt += m ? 1 : 0;
                GA_h[q * 64 + p] = m ? acc : 0.0f;
            }
        } else {
#pragma unroll
            for (int q = 8; q < 16; q++) {
                float acc = 0.f;
#pragma unroll
                for (int k = 0; k < 8; k++)
                    acc += DKc(q, k) * ((q & 1) ? d8[k] : s8[k]);
                bool m = fabsf(acc) > 0.135f;
                cnt += m ? 1 : 0;
                GA_h[q * 64 + p] = m ? acc : 0.0f;
            }
        }
        cnt = __reduce_add_sync(0xffffffffu, cnt);
        if (lane == 0) atomicAdd(&snnz[half], cnt);
    }
    __syncthreads();
    float wgt = 400.0f / fmaxf((float)snnz[half], 1.0f);

    // --- second DK apply (ref bug), even/odd -> GB ---
    if (active) {
        float g[16];
#pragma unroll
        for (int k = 0; k < 16; k++) g[k] = GA_h[k * 64 + p];
        float s2[8], d2[8];
#pragma unroll
        for (int k = 0; k < 8; k++) {
            s2[k] = g[k] + g[15 - k];
            d2[k] = g[k] - g[15 - k];
        }
        if (ht < 64) {
#pragma unroll
            for (int q = 0; q < 8; q++) {
                float acc = 0.f;
#pragma unroll
                for (int k = 0; k < 8; k++)
                    acc += DKc(q, k) * ((q & 1) ? d2[k] : s2[k]);
                GB_h[q * 64 + p] = acc;
            }
        } else {
#pragma unroll
            for (int q = 8; q < 16; q++) {
                float acc = 0.f;
#pragma unroll
                for (int k = 0; k < 8; k++)
                    acc += DKc(q, k) * ((q & 1) ? d2[k] : s2[k]);
                GB_h[q * 64 + p] = acc;
            }
        }
    }
    __syncthreads();   // GA reads done -> GA writable by stage 5

    // --- 2D inverse stage 1: GB rows -> GA ---
    if (active) {
        int hh = ht >> 6;
        int a = p >> 3, y = p & 7;
#pragma unroll
        for (int q = 0; q < 8; q++) {
            int k = hh * 8 + q;
            const float* gb = &GB_h[k * 64 + a * 8];
            float4 b0 = *(const float4*)(gb);
            float4 b1 = *(const float4*)(gb + 4);
            float acc = b0.x * sD[0 * 8 + y] + b0.y * sD[1 * 8 + y] +
                        b0.z * sD[2 * 8 + y] + b0.w * sD[3 * 8 + y] +
                        b1.x * sD[4 * 8 + y] + b1.y * sD[5 * 8 + y] +
                        b1.z * sD[6 * 8 + y] + b1.w * sD[7 * 8 + y];
            GA_h[k * 64 + p] = acc;
        }
    }
    __syncthreads();

    // --- 2D inverse stage 2 + num-only quad scatter + W update ---
    if (active) {
        for (int item = ht; item < 256; item += 128) {
            int k = item >> 4;
            int rem = item & 15;
            int b = rem >> 1;
            int qc = (rem & 1) * 4;
            float o0 = 0.f, o1 = 0.f, o2 = 0.f, o3 = 0.f;
#pragma unroll
            for (int a = 0; a < 8; a++) {
                float dv = sD[a * 8 + b];
                float4 ga = *(const float4*)(&GA_h[k * 64 + a * 8 + qc]);
                o0 += dv * ga.x;
                o1 += dv * ga.y;
                o2 += dv * ga.z;
                o3 += dv * ga.w;
            }
            int row = selYs[half][k] + b;
            int col = selXs[half][k] + qc;
            float4 v = make_float4(wgt * o0, wgt * o1, wgt * o2, wgt * o3);
            atomicAdd((float4*)(numImg + row * WW + col), v);
        }
        if (ht < KSEL) {
            int ci = selYs[half][ht] >> 2;
            int cj = selXs[half][ht] >> 2;
            atomicAdd(&Wimg[ci * NBLK + cj], wgt);
        }
    }
}

// ---------------------------------------------------------------------------
// Final divide: cnt reconstructed from the per-origin weight map.
// ---------------------------------------------------------------------------
__global__ void div_kernel(float* __restrict__ out) {
    int idx = blockIdx.x * blockDim.x + threadIdx.x;
    int img = idx >> 16;
    int y = (idx >> 8) & 255;
    int x = idx & 255;
    const float* Wimg = g_W + img * (NBLK * NBLK);

    int ayh = min(NBLK - 1, y >> 2);
    int ayl = ayh - 1;
    bool vy = (ayl >= 0) && (ayl * 4 + 7 >= y);
    int axh = min(NBLK - 1, x >> 2);
    int axl = axh - 1;
    bool vx = (axl >= 0) && (axl * 4 + 7 >= x);

    float cnt = Wimg[ayh * NBLK + axh];
    if (vx) cnt += Wimg[ayh * NBLK + axl];
    if (vy) cnt += Wimg[ayl * NBLK + axh];
    if (vy && vx) cnt += Wimg[ayl * NBLK + axl];

    out[idx] = g_num[idx] / fmaxf(cnt, 1e-8f);
}

// ---------------------------------------------------------------------------
extern "C" void kernel_launch(void* const* d_in, const int* in_sizes, int n_in,
                              void* d_out, int out_size) {
    const float* x = (const float*)d_in[0];
    (void)in_sizes; (void)n_in; (void)out_size;

    zero_kernel<<<544, 256>>>();                                 // idx 0
    dct_kernel<<<(NIMG * NBLK * NBLK + 3) / 4, 256>>>(x);        // idx 1
    nop_kernel<<<1, 32>>>();                                     // idx 2
    bm3d_kernel<<<dim3(NIMG, 32, NBLK), 256>>>();                // idx 3 <- ncu capture slot
    div_kernel<<<2048, 256>>>((float*)d_out);                    // idx 4
}